// round 12
// baseline (speedup 1.0000x reference)
#include <cuda_runtime.h>
#include <cuda_fp16.h>
#include <cstdint>
#include <math.h>

// Problem constants
constexpr int B  = 4;
constexpr int N  = 2048;
constexpr int D  = 1024;
constexpr int H  = 16;
constexpr int DK = 64;
constexpr int HD = H * DK;   // 1024

// ---------------------------------------------------------------------------
// Scratch (device globals — no allocation allowed). fp16 storage.
// Q keeps a lo array (feeds logits); K/V are pure fp16 (storage-quant bound).
// ---------------------------------------------------------------------------
__device__ __half g_Qhi[(size_t)B * H * N * DK];  // [bh][n][dk], pre-scaled 0.125
__device__ __half g_Qlo[(size_t)B * H * N * DK];
__device__ __half g_Khi[(size_t)B * H * N * DK];
__device__ __half g_Vhi[(size_t)B * H * N * DK];
__device__ __half g_Xhi[(size_t)B * N * D];       // X split, [m][k]
__device__ __half g_Xlo[(size_t)B * N * D];
__device__ __half g_WThi[4][(size_t)D * HD];      // W^T fp16, [n][k] (0=q,1=k,2=v,3=o)
__device__ __half g_AThi[(size_t)B * N * HD];     // attention out split, [m][k]
__device__ __half g_ATlo[(size_t)B * N * HD];

// ---------------------------------------------------------------------------
// PTX helpers (generic sm_80+ path — harness PTX targets compute_103, which
// rejects tcgen05/'a'-suffix features; legacy HMMA/ldmatrix/cp.async only)
// ---------------------------------------------------------------------------
__device__ __forceinline__ uint32_t smem_u32(const void* p) {
    uint32_t a;
    asm("{ .reg .u64 t; cvta.to.shared.u64 t, %1; cvt.u32.u64 %0, t; }" : "=r"(a) : "l"(p));
    return a;
}
__device__ __forceinline__ void cp16(uint32_t dst, const void* src) {
    asm volatile("cp.async.cg.shared.global [%0], [%1], 16;" :: "r"(dst), "l"(src));
}
#define CP_COMMIT() asm volatile("cp.async.commit_group;" ::: "memory")
#define CP_WAIT(n)  asm volatile("cp.async.wait_group %0;" :: "n"(n) : "memory")

__device__ __forceinline__ void ldsm4(uint32_t& r0, uint32_t& r1, uint32_t& r2, uint32_t& r3,
                                      uint32_t addr) {
    asm volatile("ldmatrix.sync.aligned.m8n8.x4.shared.b16 {%0,%1,%2,%3}, [%4];"
                 : "=r"(r0), "=r"(r1), "=r"(r2), "=r"(r3) : "r"(addr));
}
__device__ __forceinline__ void ldsm4t(uint32_t& r0, uint32_t& r1, uint32_t& r2, uint32_t& r3,
                                       uint32_t addr) {
    asm volatile("ldmatrix.sync.aligned.m8n8.x4.trans.shared.b16 {%0,%1,%2,%3}, [%4];"
                 : "=r"(r0), "=r"(r1), "=r"(r2), "=r"(r3) : "r"(addr));
}
// fp16 inputs, fp32 accumulate
__device__ __forceinline__ void mma16816(float* c,
                                         uint32_t a0, uint32_t a1, uint32_t a2, uint32_t a3,
                                         uint32_t b0, uint32_t b1) {
    asm volatile("mma.sync.aligned.m16n8k16.row.col.f32.f16.f16.f32 "
                 "{%0,%1,%2,%3}, {%4,%5,%6,%7}, {%8,%9}, {%0,%1,%2,%3};"
                 : "+f"(c[0]), "+f"(c[1]), "+f"(c[2]), "+f"(c[3])
                 : "r"(a0), "r"(a1), "r"(a2), "r"(a3), "r"(b0), "r"(b1));
}
// split v0,v1 into packed fp16 hi pair (return) and lo pair (out param)
__device__ __forceinline__ uint32_t packsplit(float v0, float v1, uint32_t& lo) {
    const __half h0 = __float2half_rn(v0);
    const __half h1 = __float2half_rn(v1);
    __half2 hp; hp.x = h0; hp.y = h1;
    __half2 lp;
    lp.x = __float2half_rn(v0 - __half2float(h0));
    lp.y = __float2half_rn(v1 - __half2float(h1));
    lo = *reinterpret_cast<uint32_t*>(&lp);
    return *reinterpret_cast<uint32_t*>(&hp);
}
__device__ __forceinline__ uint32_t packh2(float v0, float v1) {
    __half2 hp; hp.x = __float2half_rn(v0); hp.y = __float2half_rn(v1);
    return *reinterpret_cast<uint32_t*>(&hp);
}

// ---------------------------------------------------------------------------
// fp16 HMMA GEMM body: C[128,128] = A[128,1024]@B, B given as B^T [n][k].
// USE_AL=1: C = Ah*Bh + Al*Bh (2-product, A-corrected)
// USE_AL=0: C = Ah*Bh        (1-product, pure fp16)
// 4-stage cp.async ring, single __syncthreads per K-chunk. f32 accumulate.
// ---------------------------------------------------------------------------
constexpr int APITCH_B = 80;
constexpr int ARR_B    = 128 * APITCH_B;     // 10240

template <bool USE_AL>
__device__ __forceinline__ void gemm_mma_body(
    const __half* __restrict__ Ahi, const __half* __restrict__ Alo,
    const __half* __restrict__ Bhi,
    int rowBase, int colBase, char* sm, float acc[4][4][4])
{
    constexpr int NARR = USE_AL ? 3 : 2;
    constexpr int STG  = NARR * ARR_B;
    constexpr int BOFF = (NARR - 1) * ARR_B;   // Bhi array offset within stage
    const int tid  = threadIdx.x;
    const int lane = tid & 31;
    const int w    = tid >> 5;
    const int wm   = (w >> 2) * 64;
    const int wn   = (w & 3) * 32;
    const uint32_t sb = smem_u32(sm);

    auto load_stage = [&](int s, int k0) {
        const uint32_t base = sb + s * STG;
        #pragma unroll
        for (int a = 0; a < NARR; ++a) {
            const __half* src = (a == 0) ? Ahi : (USE_AL && a == 1) ? Alo : Bhi;
            const int rb = (a < NARR - 1) ? rowBase : colBase;
            #pragma unroll
            for (int t = 0; t < 2; ++t) {
                const int idx = tid * 2 + t;
                const int r = idx >> 2, ch = idx & 3;
                cp16(base + a * ARR_B + r * APITCH_B + ch * 16,
                     src + (size_t)(rb + r) * D + k0 + ch * 8);
            }
        }
    };

    auto comp = [&](int s) {
        const uint32_t base = sb + s * STG;
        #pragma unroll
        for (int k16 = 0; k16 < 2; ++k16) {
            uint32_t Ah[4][4], Al[4][4], Bh[2][4];
            #pragma unroll
            for (int mi = 0; mi < 4; ++mi) {
                const uint32_t addr = base + (wm + mi * 16 + (lane & 15)) * APITCH_B
                                      + k16 * 32 + (lane >> 4) * 16;
                ldsm4(Ah[mi][0], Ah[mi][1], Ah[mi][2], Ah[mi][3], addr);
                if (USE_AL)
                    ldsm4(Al[mi][0], Al[mi][1], Al[mi][2], Al[mi][3], addr + ARR_B);
            }
            #pragma unroll
            for (int np = 0; np < 2; ++np) {
                const int nrow = wn + np * 16 + (lane & 7) + ((lane >> 4) << 3);
                const uint32_t addr = base + BOFF + nrow * APITCH_B
                                      + k16 * 32 + ((lane >> 3) & 1) * 16;
                ldsm4(Bh[np][0], Bh[np][1], Bh[np][2], Bh[np][3], addr);
            }
            // Ah*Bh (16 independent accs)
            #pragma unroll
            for (int mi = 0; mi < 4; ++mi)
                #pragma unroll
                for (int nf = 0; nf < 4; ++nf) {
                    const int np = nf >> 1, hh = (nf & 1) * 2;
                    mma16816(acc[mi][nf], Ah[mi][0], Ah[mi][1], Ah[mi][2], Ah[mi][3],
                             Bh[np][hh], Bh[np][hh + 1]);
                }
            // Al*Bh (A-corrected path only)
            if (USE_AL) {
                #pragma unroll
                for (int mi = 0; mi < 4; ++mi)
                    #pragma unroll
                    for (int nf = 0; nf < 4; ++nf) {
                        const int np = nf >> 1, hh = (nf & 1) * 2;
                        mma16816(acc[mi][nf], Al[mi][0], Al[mi][1], Al[mi][2], Al[mi][3],
                                 Bh[np][hh], Bh[np][hh + 1]);
                    }
            }
        }
    };

    constexpr int NC = D / 32;   // 32 chunks
    load_stage(0, 0);            CP_COMMIT();
    load_stage(1, 32);           CP_COMMIT();
    load_stage(2, 64);           CP_COMMIT();
    for (int c = 0; c < NC; ++c) {
        CP_WAIT(2);
        __syncthreads();
        if (c + 3 < NC) load_stage((c + 3) & 3, (c + 3) * 32);
        CP_COMMIT();
        comp(c & 3);
    }
}

constexpr int GSMEM = 4 * 3 * ARR_B;   // 122880 (max: 3-array stages)

// QKV projection. z=0 (Q): 2-product, epilogue hi+lo pre-scaled.
// z=1,2 (K,V): 1-product pure fp16 (storage quantization dominates anyway).
__global__ __launch_bounds__(256, 1) void qkv_mma() {
    extern __shared__ char sm[];
    const int z = blockIdx.z;
    const int rowBase = blockIdx.y * 128, colBase = blockIdx.x * 128;
    float acc[4][4][4];
    #pragma unroll
    for (int i = 0; i < 4; ++i)
        #pragma unroll
        for (int j = 0; j < 4; ++j)
            #pragma unroll
            for (int k = 0; k < 4; ++k) acc[i][j][k] = 0.f;

    if (z == 0)
        gemm_mma_body<true>(g_Xhi, g_Xlo, g_WThi[0], rowBase, colBase, sm, acc);
    else
        gemm_mma_body<false>(g_Xhi, nullptr, g_WThi[z], rowBase, colBase, sm, acc);

    const int lane = threadIdx.x & 31, w = threadIdx.x >> 5;
    const int wm = (w >> 2) * 64, wn = (w & 3) * 32;
    #pragma unroll
    for (int mi = 0; mi < 4; ++mi)
        #pragma unroll
        for (int nf = 0; nf < 4; ++nf) {
            const int r0 = rowBase + wm + mi * 16 + (lane >> 2);
            const int c0 = colBase + wn + nf * 8 + (lane & 3) * 2;
            const int hh = c0 >> 6, dd = c0 & 63;
            #pragma unroll
            for (int rr = 0; rr < 2; ++rr) {
                const int r = r0 + rr * 8;
                const int b = r >> 11, n = r & (N - 1);
                const size_t idx = (((size_t)(b * H + hh)) * N + n) * DK + dd;
                const float v0 = acc[mi][nf][rr * 2], v1 = acc[mi][nf][rr * 2 + 1];
                if (z == 0) {
                    uint32_t lo;
                    const uint32_t hi = packsplit(v0 * 0.125f, v1 * 0.125f, lo);
                    *reinterpret_cast<uint32_t*>(g_Qhi + idx) = hi;
                    *reinterpret_cast<uint32_t*>(g_Qlo + idx) = lo;
                } else {
                    __half* Ohi = (z == 1) ? g_Khi : g_Vhi;
                    *reinterpret_cast<uint32_t*>(Ohi + idx) = packh2(v0, v1);
                }
            }
        }
}

// Output projection (2-product, AT-corrected): AT @ Wo -> d_out fp32
__global__ __launch_bounds__(256, 1) void out_mma(float* __restrict__ Cout) {
    extern __shared__ char sm[];
    const int rowBase = blockIdx.y * 128, colBase = blockIdx.x * 128;
    float acc[4][4][4];
    #pragma unroll
    for (int i = 0; i < 4; ++i)
        #pragma unroll
        for (int j = 0; j < 4; ++j)
            #pragma unroll
            for (int k = 0; k < 4; ++k) acc[i][j][k] = 0.f;

    gemm_mma_body<true>(g_AThi, g_ATlo, g_WThi[3], rowBase, colBase, sm, acc);

    const int lane = threadIdx.x & 31, w = threadIdx.x >> 5;
    const int wm = (w >> 2) * 64, wn = (w & 3) * 32;
    #pragma unroll
    for (int mi = 0; mi < 4; ++mi)
        #pragma unroll
        for (int nf = 0; nf < 4; ++nf) {
            const int r0 = rowBase + wm + mi * 16 + (lane >> 2);
            const int c0 = colBase + wn + nf * 8 + (lane & 3) * 2;
            #pragma unroll
            for (int e = 0; e < 4; ++e)
                Cout[(size_t)(r0 + (e >> 1) * 8) * HD + c0 + (e & 1)] = acc[mi][nf][e];
        }
}

// ---------------------------------------------------------------------------
// Precision-split conversion passes
// ---------------------------------------------------------------------------
__global__ void convX(const float* __restrict__ X) {
    const size_t i = ((size_t)blockIdx.x * 256 + threadIdx.x) * 2;
    const float2 v = *(const float2*)(X + i);
    uint32_t lo;
    const uint32_t hi = packsplit(v.x, v.y, lo);
    *reinterpret_cast<uint32_t*>(g_Xhi + i) = hi;
    *reinterpret_cast<uint32_t*>(g_Xlo + i) = lo;
}

// Transpose W -> WT[n][k], fp16 (no lo arrays needed anymore)
__global__ void convW(const float* __restrict__ Wq, const float* __restrict__ Wk,
                      const float* __restrict__ Wv, const float* __restrict__ Wo) {
    const int z = blockIdx.z;
    const float* W = (z == 0) ? Wq : (z == 1) ? Wk : (z == 2) ? Wv : Wo;
    __half* Th = g_WThi[z];
    __shared__ float t[32][33];
    const int k0 = blockIdx.x * 32, n0 = blockIdx.y * 32;
    #pragma unroll
    for (int j = 0; j < 32; j += 8)
        t[threadIdx.y + j][threadIdx.x] = W[(size_t)(k0 + threadIdx.y + j) * HD + n0 + threadIdx.x];
    __syncthreads();
    #pragma unroll
    for (int j = 0; j < 32; j += 8) {
        const int n = n0 + threadIdx.y + j, k = k0 + threadIdx.x;
        Th[(size_t)n * D + k] = __float2half_rn(t[threadIdx.x][threadIdx.y + j]);
    }
}

// ---------------------------------------------------------------------------
// Tensor-core flash attention (causal):
// S = Qh*Kh + Ql*Kh (2-product — logits stay Q-corrected).
// O = Ph*Vh (1-product — P quantization accepted, probs in [0,1]).
// 128 q-rows per CTA, 8 warps. 3-stage KV ring (Kh|Vh), f32 acc.
// ---------------------------------------------------------------------------
constexpr int FP     = 144;            // smem pitch (128B data + 16B pad)
constexpr int KVARR  = 64 * FP;        // 9216
constexpr int KVSTG  = 2 * KVARR;      // Kh|Vh: 18432
constexpr int QARR   = 128 * FP;       // 18432
constexpr int FSTAGES = 3;
constexpr int FSMEM  = 2 * QARR + FSTAGES * KVSTG;   // 92160

__global__ __launch_bounds__(256, 1)
void flash_mma() {
    extern __shared__ char sm[];
    const uint32_t sb = smem_u32(sm);
    const int tid = threadIdx.x, lane = tid & 31, w = tid >> 5;
    const int bh = blockIdx.y;
    const int qt = gridDim.x - 1 - blockIdx.x;        // long blocks first
    const int q0 = qt * 128;
    const int b = bh >> 4, h = bh & (H - 1);
    const int wm = w * 16;

    const __half* Qh = g_Qhi + (size_t)bh * N * DK;
    const __half* Ql = g_Qlo + (size_t)bh * N * DK;
    const __half* Kh = g_Khi + (size_t)bh * N * DK;
    const __half* Vh = g_Vhi + (size_t)bh * N * DK;

    const uint32_t qhiS = sb, qloS = sb + QARR, stS = sb + 2 * QARR;

    auto load_kv = [&](int s, int j0) {
        const uint32_t base = stS + s * KVSTG;
        #pragma unroll
        for (int t = 0; t < 2; ++t) {
            const int i = tid + t * 256;
            const int r = i >> 3, ch = i & 7;
            const uint32_t off = r * FP + ch * 16;
            const size_t gi = (size_t)(j0 + r) * DK + ch * 8;
            cp16(base + off,         Kh + gi);
            cp16(base + KVARR + off, Vh + gi);
        }
    };

    const int jmax = 2 * qt + 1;

    for (int i = tid; i < 1024; i += 256) {
        const int r = i >> 3, ch = i & 7;
        const size_t gi = (size_t)(q0 + r) * DK + ch * 8;
        cp16(qhiS + r * FP + ch * 16, Qh + gi);
        cp16(qloS + r * FP + ch * 16, Ql + gi);
    }
    load_kv(0, 0);
    CP_COMMIT();
    load_kv(1, 64);
    CP_COMMIT();

    float m0 = -1e30f, m1 = -1e30f, l0 = 0.f, l1 = 0.f;
    float oAcc[8][4];
    #pragma unroll
    for (int i = 0; i < 8; ++i)
        #pragma unroll
        for (int e = 0; e < 4; ++e) oAcc[i][e] = 0.f;

    uint32_t qah[4][4], qal[4][4];
    bool qloaded = false;
    int kvbuf = 0;

    for (int jt = 0; jt <= jmax; ++jt) {
        const int j0 = jt * 64;
        CP_WAIT(1);
        __syncthreads();
        if (jt + 2 <= jmax) {
            int nb = kvbuf + 2; if (nb >= 3) nb -= 3;
            load_kv(nb, (jt + 2) * 64);
        }
        CP_COMMIT();

        if (!qloaded) {
            #pragma unroll
            for (int kf = 0; kf < 4; ++kf) {
                const uint32_t addr = qhiS + (wm + (lane & 15)) * FP + kf * 32 + (lane >> 4) * 16;
                ldsm4(qah[kf][0], qah[kf][1], qah[kf][2], qah[kf][3], addr);
                ldsm4(qal[kf][0], qal[kf][1], qal[kf][2], qal[kf][3], addr + QARR);
            }
            qloaded = true;
        }

        const uint32_t khS = stS + kvbuf * KVSTG;
        const uint32_t vhS = khS + KVARR;
        if (++kvbuf == 3) kvbuf = 0;

        // ---- S = (Qh + Ql) @ Kh^T ----
        float s[8][4];
        #pragma unroll
        for (int i = 0; i < 8; ++i)
            #pragma unroll
            for (int e = 0; e < 4; ++e) s[i][e] = 0.f;

        #pragma unroll
        for (int kf = 0; kf < 4; ++kf) {
            uint32_t kb[4][4];
            #pragma unroll
            for (int ng = 0; ng < 4; ++ng) {
                const uint32_t addr = khS + (ng * 16 + (lane & 7) + ((lane >> 4) << 3)) * FP
                                      + kf * 32 + ((lane >> 3) & 1) * 16;
                ldsm4(kb[ng][0], kb[ng][1], kb[ng][2], kb[ng][3], addr);
            }
            #pragma unroll
            for (int ng = 0; ng < 4; ++ng)
                #pragma unroll
                for (int nf = 0; nf < 2; ++nf)
                    mma16816(s[ng * 2 + nf], qah[kf][0], qah[kf][1], qah[kf][2], qah[kf][3],
                             kb[ng][nf * 2], kb[ng][nf * 2 + 1]);
            #pragma unroll
            for (int ng = 0; ng < 4; ++ng)
                #pragma unroll
                for (int nf = 0; nf < 2; ++nf)
                    mma16816(s[ng * 2 + nf], qal[kf][0], qal[kf][1], qal[kf][2], qal[kf][3],
                             kb[ng][nf * 2], kb[ng][nf * 2 + 1]);
        }

        // ---- causal mask ----
        const int gr0 = q0 + wm + (lane >> 2);
        if (j0 + 64 > q0 + wm) {
            #pragma unroll
            for (int ni = 0; ni < 8; ++ni)
                #pragma unroll
                for (int e = 0; e < 4; ++e) {
                    const int col = j0 + ni * 8 + (lane & 3) * 2 + (e & 1);
                    const int row = gr0 + (e >> 1) * 8;
                    if (col > row) s[ni][e] = -1e30f;
                }
        }

        // ---- online softmax ----
        float rm0 = -1e30f, rm1 = -1e30f;
        #pragma unroll
        for (int ni = 0; ni < 8; ++ni) {
            rm0 = fmaxf(rm0, fmaxf(s[ni][0], s[ni][1]));
            rm1 = fmaxf(rm1, fmaxf(s[ni][2], s[ni][3]));
        }
        rm0 = fmaxf(rm0, __shfl_xor_sync(0xffffffffu, rm0, 1));
        rm0 = fmaxf(rm0, __shfl_xor_sync(0xffffffffu, rm0, 2));
        rm1 = fmaxf(rm1, __shfl_xor_sync(0xffffffffu, rm1, 1));
        rm1 = fmaxf(rm1, __shfl_xor_sync(0xffffffffu, rm1, 2));

        const float mn0 = fmaxf(m0, rm0), mn1 = fmaxf(m1, rm1);
        const float a0 = __expf(m0 - mn0), a1 = __expf(m1 - mn1);
        m0 = mn0; m1 = mn1;

        float rs0 = 0.f, rs1 = 0.f;
        #pragma unroll
        for (int ni = 0; ni < 8; ++ni) {
            s[ni][0] = __expf(s[ni][0] - mn0); rs0 += s[ni][0];
            s[ni][1] = __expf(s[ni][1] - mn0); rs0 += s[ni][1];
            s[ni][2] = __expf(s[ni][2] - mn1); rs1 += s[ni][2];
            s[ni][3] = __expf(s[ni][3] - mn1); rs1 += s[ni][3];
        }
        rs0 += __shfl_xor_sync(0xffffffffu, rs0, 1);
        rs0 += __shfl_xor_sync(0xffffffffu, rs0, 2);
        rs1 += __shfl_xor_sync(0xffffffffu, rs1, 1);
        rs1 += __shfl_xor_sync(0xffffffffu, rs1, 2);
        l0 = l0 * a0 + rs0;
        l1 = l1 * a1 + rs1;

        #pragma unroll
        for (int ni = 0; ni < 8; ++ni) {
            oAcc[ni][0] *= a0; oAcc[ni][1] *= a0;
            oAcc[ni][2] *= a1; oAcc[ni][3] *= a1;
        }

        // ---- P -> fp16 A-fragments (quantization accepted) ----
        uint32_t pah[4][4];
        #pragma unroll
        for (int kf = 0; kf < 4; ++kf) {
            pah[kf][0] = packh2(s[2 * kf][0],     s[2 * kf][1]);
            pah[kf][1] = packh2(s[2 * kf][2],     s[2 * kf][3]);
            pah[kf][2] = packh2(s[2 * kf + 1][0], s[2 * kf + 1][1]);
            pah[kf][3] = packh2(s[2 * kf + 1][2], s[2 * kf + 1][3]);
        }

        // ---- O += Ph @ Vh ----
        #pragma unroll
        for (int kf = 0; kf < 4; ++kf) {
            uint32_t vb[4][4];
            #pragma unroll
            for (int ng = 0; ng < 4; ++ng) {
                const uint32_t addr = vhS + (kf * 16 + (lane & 15)) * FP
                                      + ng * 32 + (lane >> 4) * 16;
                ldsm4t(vb[ng][0], vb[ng][1], vb[ng][2], vb[ng][3], addr);
            }
            #pragma unroll
            for (int ng = 0; ng < 4; ++ng)
                #pragma unroll
                for (int nf = 0; nf < 2; ++nf)
                    mma16816(oAcc[ng * 2 + nf], pah[kf][0], pah[kf][1], pah[kf][2], pah[kf][3],
                             vb[ng][nf * 2], vb[ng][nf * 2 + 1]);
        }
        // no trailing sync: 3-stage ring + top-of-loop barrier covers reuse
    }

    // ---- epilogue: normalize, split to fp16 hi/lo for output projection ----
    const float inv0 = 1.0f / l0, inv1 = 1.0f / l1;
    const int r0 = q0 + wm + (lane >> 2);
    #pragma unroll
    for (int ni = 0; ni < 8; ++ni) {
        const int col = h * DK + ni * 8 + (lane & 3) * 2;
        uint32_t lo;
        uint32_t hi = packsplit(oAcc[ni][0] * inv0, oAcc[ni][1] * inv0, lo);
        size_t idx = ((size_t)b * N + r0) * HD + col;
        *reinterpret_cast<uint32_t*>(g_AThi + idx) = hi;
        *reinterpret_cast<uint32_t*>(g_ATlo + idx) = lo;
        hi = packsplit(oAcc[ni][2] * inv1, oAcc[ni][3] * inv1, lo);
        idx = ((size_t)b * N + r0 + 8) * HD + col;
        *reinterpret_cast<uint32_t*>(g_AThi + idx) = hi;
        *reinterpret_cast<uint32_t*>(g_ATlo + idx) = lo;
    }
}

// ---------------------------------------------------------------------------
extern "C" void kernel_launch(void* const* d_in, const int* in_sizes, int n_in,
                              void* d_out, int out_size) {
    const float* X  = (const float*)d_in[0];
    // d_in[1] = mask (pure causal -> applied analytically)
    const float* Wq = (const float*)d_in[2];
    const float* Wk = (const float*)d_in[3];
    const float* Wv = (const float*)d_in[4];
    const float* Wo = (const float*)d_in[5];
    float* out = (float*)d_out;

    cudaFuncSetAttribute(qkv_mma,   cudaFuncAttributeMaxDynamicSharedMemorySize, GSMEM);
    cudaFuncSetAttribute(out_mma,   cudaFuncAttributeMaxDynamicSharedMemorySize, GSMEM);
    cudaFuncSetAttribute(flash_mma, cudaFuncAttributeMaxDynamicSharedMemorySize, FSMEM);

    // 0) conversions
    convX<<<(B * N * D / 2) / 256, 256>>>(X);
    convW<<<dim3(D / 32, HD / 32, 4), dim3(32, 8)>>>(Wq, Wk, Wv, Wo);

    // 1) QKV projections (Q: 2-product; K,V: 1-product)
    qkv_mma<<<dim3(HD / 128, (B * N) / 128, 3), 256, GSMEM>>>();   // (8, 64, 3)

    // 2) causal flash attention (S: 2-product; PV: 1-product)
    flash_mma<<<dim3(N / 128, B * H), 256, FSMEM>>>();             // (16, 64)

    // 3) output projection (2-product, AT-corrected)
    out_mma<<<dim3(HD / 128, (B * N) / 128), 256, GSMEM>>>(out);   // (8, 64)
}

// round 13
// speedup vs baseline: 1.2767x; 1.2767x over previous
#include <cuda_runtime.h>
#include <cuda_fp16.h>
#include <cstdint>
#include <math.h>

// Problem constants
constexpr int B  = 4;
constexpr int N  = 2048;
constexpr int D  = 1024;
constexpr int H  = 16;
constexpr int DK = 64;
constexpr int HD = H * DK;   // 1024

// ---------------------------------------------------------------------------
// Scratch (device globals — no allocation allowed). fp16 storage.
// Q keeps a lo array (feeds logits); K/V pure fp16 (storage-quant bound).
// W^T is fp16-only (A-side corrections carry the precision).
// ---------------------------------------------------------------------------
__device__ __half g_Qhi[(size_t)B * H * N * DK];  // [bh][n][dk], pre-scaled 0.125
__device__ __half g_Qlo[(size_t)B * H * N * DK];
__device__ __half g_Khi[(size_t)B * H * N * DK];
__device__ __half g_Vhi[(size_t)B * H * N * DK];
__device__ __half g_Xhi[(size_t)B * N * D];       // X split, [m][k]
__device__ __half g_Xlo[(size_t)B * N * D];
__device__ __half g_WThi[4][(size_t)D * HD];      // W^T fp16, [n][k] (0=q,1=k,2=v,3=o)
__device__ __half g_AThi[(size_t)B * N * HD];     // attention out split, [m][k]
__device__ __half g_ATlo[(size_t)B * N * HD];

// ---------------------------------------------------------------------------
// PTX helpers (generic sm_80+ path — harness PTX targets compute_103, which
// rejects tcgen05/'a'-suffix features; legacy HMMA/ldmatrix/cp.async only)
// ---------------------------------------------------------------------------
__device__ __forceinline__ uint32_t smem_u32(const void* p) {
    uint32_t a;
    asm("{ .reg .u64 t; cvta.to.shared.u64 t, %1; cvt.u32.u64 %0, t; }" : "=r"(a) : "l"(p));
    return a;
}
__device__ __forceinline__ void cp16(uint32_t dst, const void* src) {
    asm volatile("cp.async.cg.shared.global [%0], [%1], 16;" :: "r"(dst), "l"(src));
}
#define CP_COMMIT() asm volatile("cp.async.commit_group;" ::: "memory")
#define CP_WAIT(n)  asm volatile("cp.async.wait_group %0;" :: "n"(n) : "memory")

__device__ __forceinline__ void ldsm4(uint32_t& r0, uint32_t& r1, uint32_t& r2, uint32_t& r3,
                                      uint32_t addr) {
    asm volatile("ldmatrix.sync.aligned.m8n8.x4.shared.b16 {%0,%1,%2,%3}, [%4];"
                 : "=r"(r0), "=r"(r1), "=r"(r2), "=r"(r3) : "r"(addr));
}
__device__ __forceinline__ void ldsm4t(uint32_t& r0, uint32_t& r1, uint32_t& r2, uint32_t& r3,
                                       uint32_t addr) {
    asm volatile("ldmatrix.sync.aligned.m8n8.x4.trans.shared.b16 {%0,%1,%2,%3}, [%4];"
                 : "=r"(r0), "=r"(r1), "=r"(r2), "=r"(r3) : "r"(addr));
}
// fp16 inputs, fp32 accumulate
__device__ __forceinline__ void mma16816(float* c,
                                         uint32_t a0, uint32_t a1, uint32_t a2, uint32_t a3,
                                         uint32_t b0, uint32_t b1) {
    asm volatile("mma.sync.aligned.m16n8k16.row.col.f32.f16.f16.f32 "
                 "{%0,%1,%2,%3}, {%4,%5,%6,%7}, {%8,%9}, {%0,%1,%2,%3};"
                 : "+f"(c[0]), "+f"(c[1]), "+f"(c[2]), "+f"(c[3])
                 : "r"(a0), "r"(a1), "r"(a2), "r"(a3), "r"(b0), "r"(b1));
}
// split v0,v1 into packed fp16 hi pair (return) and lo pair (out param)
__device__ __forceinline__ uint32_t packsplit(float v0, float v1, uint32_t& lo) {
    const __half h0 = __float2half_rn(v0);
    const __half h1 = __float2half_rn(v1);
    __half2 hp; hp.x = h0; hp.y = h1;
    __half2 lp;
    lp.x = __float2half_rn(v0 - __half2float(h0));
    lp.y = __float2half_rn(v1 - __half2float(h1));
    lo = *reinterpret_cast<uint32_t*>(&lp);
    return *reinterpret_cast<uint32_t*>(&hp);
}
__device__ __forceinline__ uint32_t packh2(float v0, float v1) {
    __half2 hp; hp.x = __float2half_rn(v0); hp.y = __float2half_rn(v1);
    return *reinterpret_cast<uint32_t*>(&hp);
}

// ---------------------------------------------------------------------------
// fp16 2-product HMMA GEMM body: C[128,128] = (Ah + Al) @ Bh.
// B given as B^T [n][k] fp16 (B quantization accepted, ~2.3e-4 calibrated).
// 4-stage cp.async ring (3 arrays: Ah|Al|Bh), single __syncthreads per chunk.
// This shape ran at the HMMA roofline in R11 — do not thin it further
// (1-product flips it to LDGSTS-issue-bound; measured R12).
// ---------------------------------------------------------------------------
constexpr int APITCH_B = 80;
constexpr int ARR_B    = 128 * APITCH_B;     // 10240
constexpr int STAGE_B  = 3 * ARR_B;          // 30720
constexpr int GSMEM    = 4 * STAGE_B;        // 122880

__device__ __forceinline__ void gemm_mma_body(
    const __half* __restrict__ Ahi, const __half* __restrict__ Alo,
    const __half* __restrict__ Bhi,
    int rowBase, int colBase, char* sm, float acc[4][4][4])
{
    const int tid  = threadIdx.x;
    const int lane = tid & 31;
    const int w    = tid >> 5;
    const int wm   = (w >> 2) * 64;
    const int wn   = (w & 3) * 32;
    const uint32_t sb = smem_u32(sm);

    auto load_stage = [&](int s, int k0) {
        const uint32_t base = sb + s * STAGE_B;
        #pragma unroll
        for (int a = 0; a < 3; ++a) {
            const __half* src = (a == 0) ? Ahi : (a == 1) ? Alo : Bhi;
            const int rb = (a < 2) ? rowBase : colBase;
            #pragma unroll
            for (int t = 0; t < 2; ++t) {
                const int idx = tid * 2 + t;
                const int r = idx >> 2, ch = idx & 3;
                cp16(base + a * ARR_B + r * APITCH_B + ch * 16,
                     src + (size_t)(rb + r) * D + k0 + ch * 8);
            }
        }
    };

    auto comp = [&](int s) {
        const uint32_t base = sb + s * STAGE_B;
        #pragma unroll
        for (int k16 = 0; k16 < 2; ++k16) {
            uint32_t Ah[4][4], Al[4][4], Bh[2][4];
            #pragma unroll
            for (int mi = 0; mi < 4; ++mi) {
                const uint32_t addr = base + (wm + mi * 16 + (lane & 15)) * APITCH_B
                                      + k16 * 32 + (lane >> 4) * 16;
                ldsm4(Ah[mi][0], Ah[mi][1], Ah[mi][2], Ah[mi][3], addr);
                ldsm4(Al[mi][0], Al[mi][1], Al[mi][2], Al[mi][3], addr + ARR_B);
            }
            #pragma unroll
            for (int np = 0; np < 2; ++np) {
                const int nrow = wn + np * 16 + (lane & 7) + ((lane >> 4) << 3);
                const uint32_t addr = base + 2 * ARR_B + nrow * APITCH_B
                                      + k16 * 32 + ((lane >> 3) & 1) * 16;
                ldsm4(Bh[np][0], Bh[np][1], Bh[np][2], Bh[np][3], addr);
            }
            // Ah*Bh (16 independent accs)
            #pragma unroll
            for (int mi = 0; mi < 4; ++mi)
                #pragma unroll
                for (int nf = 0; nf < 4; ++nf) {
                    const int np = nf >> 1, hh = (nf & 1) * 2;
                    mma16816(acc[mi][nf], Ah[mi][0], Ah[mi][1], Ah[mi][2], Ah[mi][3],
                             Bh[np][hh], Bh[np][hh + 1]);
                }
            // Al*Bh
            #pragma unroll
            for (int mi = 0; mi < 4; ++mi)
                #pragma unroll
                for (int nf = 0; nf < 4; ++nf) {
                    const int np = nf >> 1, hh = (nf & 1) * 2;
                    mma16816(acc[mi][nf], Al[mi][0], Al[mi][1], Al[mi][2], Al[mi][3],
                             Bh[np][hh], Bh[np][hh + 1]);
                }
        }
    };

    constexpr int NC = D / 32;   // 32 chunks
    load_stage(0, 0);            CP_COMMIT();
    load_stage(1, 32);           CP_COMMIT();
    load_stage(2, 64);           CP_COMMIT();
    for (int c = 0; c < NC; ++c) {
        CP_WAIT(2);
        __syncthreads();
        if (c + 3 < NC) load_stage((c + 3) & 3, (c + 3) * 32);
        CP_COMMIT();
        comp(c & 3);
    }
}

// QKV projection (2-product, X-corrected). z=0: Q hi+lo pre-scaled; z=1,2: fp16.
__global__ __launch_bounds__(256, 1) void qkv_mma() {
    extern __shared__ char sm[];
    const int z = blockIdx.z;
    const int rowBase = blockIdx.y * 128, colBase = blockIdx.x * 128;
    float acc[4][4][4];
    #pragma unroll
    for (int i = 0; i < 4; ++i)
        #pragma unroll
        for (int j = 0; j < 4; ++j)
            #pragma unroll
            for (int k = 0; k < 4; ++k) acc[i][j][k] = 0.f;

    gemm_mma_body(g_Xhi, g_Xlo, g_WThi[z], rowBase, colBase, sm, acc);

    const int lane = threadIdx.x & 31, w = threadIdx.x >> 5;
    const int wm = (w >> 2) * 64, wn = (w & 3) * 32;
    #pragma unroll
    for (int mi = 0; mi < 4; ++mi)
        #pragma unroll
        for (int nf = 0; nf < 4; ++nf) {
            const int r0 = rowBase + wm + mi * 16 + (lane >> 2);
            const int c0 = colBase + wn + nf * 8 + (lane & 3) * 2;
            const int hh = c0 >> 6, dd = c0 & 63;
            #pragma unroll
            for (int rr = 0; rr < 2; ++rr) {
                const int r = r0 + rr * 8;
                const int b = r >> 11, n = r & (N - 1);
                const size_t idx = (((size_t)(b * H + hh)) * N + n) * DK + dd;
                const float v0 = acc[mi][nf][rr * 2], v1 = acc[mi][nf][rr * 2 + 1];
                if (z == 0) {
                    uint32_t lo;
                    const uint32_t hi = packsplit(v0 * 0.125f, v1 * 0.125f, lo);
                    *reinterpret_cast<uint32_t*>(g_Qhi + idx) = hi;
                    *reinterpret_cast<uint32_t*>(g_Qlo + idx) = lo;
                } else {
                    __half* Ohi = (z == 1) ? g_Khi : g_Vhi;
                    *reinterpret_cast<uint32_t*>(Ohi + idx) = packh2(v0, v1);
                }
            }
        }
}

// Output projection (2-product, AT-corrected): (AThi + ATlo) @ Wo -> fp32
__global__ __launch_bounds__(256, 1) void out_mma(float* __restrict__ Cout) {
    extern __shared__ char sm[];
    const int rowBase = blockIdx.y * 128, colBase = blockIdx.x * 128;
    float acc[4][4][4];
    #pragma unroll
    for (int i = 0; i < 4; ++i)
        #pragma unroll
        for (int j = 0; j < 4; ++j)
            #pragma unroll
            for (int k = 0; k < 4; ++k) acc[i][j][k] = 0.f;

    gemm_mma_body(g_AThi, g_ATlo, g_WThi[3], rowBase, colBase, sm, acc);

    const int lane = threadIdx.x & 31, w = threadIdx.x >> 5;
    const int wm = (w >> 2) * 64, wn = (w & 3) * 32;
    #pragma unroll
    for (int mi = 0; mi < 4; ++mi)
        #pragma unroll
        for (int nf = 0; nf < 4; ++nf) {
            const int r0 = rowBase + wm + mi * 16 + (lane >> 2);
            const int c0 = colBase + wn + nf * 8 + (lane & 3) * 2;
            #pragma unroll
            for (int e = 0; e < 4; ++e)
                Cout[(size_t)(r0 + (e >> 1) * 8) * HD + c0 + (e & 1)] = acc[mi][nf][e];
        }
}

// ---------------------------------------------------------------------------
// Precision-split conversion passes
// ---------------------------------------------------------------------------
__global__ void convX(const float* __restrict__ X) {
    const size_t i = ((size_t)blockIdx.x * 256 + threadIdx.x) * 2;
    const float2 v = *(const float2*)(X + i);
    uint32_t lo;
    const uint32_t hi = packsplit(v.x, v.y, lo);
    *reinterpret_cast<uint32_t*>(g_Xhi + i) = hi;
    *reinterpret_cast<uint32_t*>(g_Xlo + i) = lo;
}

// Transpose W -> WT[n][k], fp16 (hi only)
__global__ void convW(const float* __restrict__ Wq, const float* __restrict__ Wk,
                      const float* __restrict__ Wv, const float* __restrict__ Wo) {
    const int z = blockIdx.z;
    const float* W = (z == 0) ? Wq : (z == 1) ? Wk : (z == 2) ? Wv : Wo;
    __half* Th = g_WThi[z];
    __shared__ float t[32][33];
    const int k0 = blockIdx.x * 32, n0 = blockIdx.y * 32;
    #pragma unroll
    for (int j = 0; j < 32; j += 8)
        t[threadIdx.y + j][threadIdx.x] = W[(size_t)(k0 + threadIdx.y + j) * HD + n0 + threadIdx.x];
    __syncthreads();
    #pragma unroll
    for (int j = 0; j < 32; j += 8) {
        const int n = n0 + threadIdx.y + j, k = k0 + threadIdx.x;
        Th[(size_t)n * D + k] = __float2half_rn(t[threadIdx.x][threadIdx.y + j]);
    }
}

// ---------------------------------------------------------------------------
// Tensor-core flash attention (causal) — R11 configuration (proven 241 us):
// S = Qh*Kh + Ql*Kh (2-product).  O = Ph*Vh + Pl*Vh (2-product).
// The 2-product PV is load-bearing for SPEED too: 1-product exposed
// trans-LDSM latency at 2 warps/SMSP (R12 regression).
// 128 q-rows per CTA, 8 warps. 3-stage KV ring (Kh|Vh), f32 acc.
// ---------------------------------------------------------------------------
constexpr int FP     = 144;            // smem pitch (128B data + 16B pad)
constexpr int KVARR  = 64 * FP;        // 9216
constexpr int KVSTG  = 2 * KVARR;      // Kh|Vh: 18432
constexpr int QARR   = 128 * FP;       // 18432
constexpr int FSTAGES = 3;
constexpr int FSMEM  = 2 * QARR + FSTAGES * KVSTG;   // 92160

__global__ __launch_bounds__(256, 1)
void flash_mma() {
    extern __shared__ char sm[];
    const uint32_t sb = smem_u32(sm);
    const int tid = threadIdx.x, lane = tid & 31, w = tid >> 5;
    const int bh = blockIdx.y;
    const int qt = gridDim.x - 1 - blockIdx.x;        // long blocks first
    const int q0 = qt * 128;
    const int b = bh >> 4, h = bh & (H - 1);
    const int wm = w * 16;

    const __half* Qh = g_Qhi + (size_t)bh * N * DK;
    const __half* Ql = g_Qlo + (size_t)bh * N * DK;
    const __half* Kh = g_Khi + (size_t)bh * N * DK;
    const __half* Vh = g_Vhi + (size_t)bh * N * DK;

    const uint32_t qhiS = sb, qloS = sb + QARR, stS = sb + 2 * QARR;

    auto load_kv = [&](int s, int j0) {
        const uint32_t base = stS + s * KVSTG;
        #pragma unroll
        for (int t = 0; t < 2; ++t) {
            const int i = tid + t * 256;
            const int r = i >> 3, ch = i & 7;
            const uint32_t off = r * FP + ch * 16;
            const size_t gi = (size_t)(j0 + r) * DK + ch * 8;
            cp16(base + off,         Kh + gi);
            cp16(base + KVARR + off, Vh + gi);
        }
    };

    const int jmax = 2 * qt + 1;

    for (int i = tid; i < 1024; i += 256) {
        const int r = i >> 3, ch = i & 7;
        const size_t gi = (size_t)(q0 + r) * DK + ch * 8;
        cp16(qhiS + r * FP + ch * 16, Qh + gi);
        cp16(qloS + r * FP + ch * 16, Ql + gi);
    }
    load_kv(0, 0);
    CP_COMMIT();
    load_kv(1, 64);
    CP_COMMIT();

    float m0 = -1e30f, m1 = -1e30f, l0 = 0.f, l1 = 0.f;
    float oAcc[8][4];
    #pragma unroll
    for (int i = 0; i < 8; ++i)
        #pragma unroll
        for (int e = 0; e < 4; ++e) oAcc[i][e] = 0.f;

    uint32_t qah[4][4], qal[4][4];
    bool qloaded = false;
    int kvbuf = 0;

    for (int jt = 0; jt <= jmax; ++jt) {
        const int j0 = jt * 64;
        CP_WAIT(1);
        __syncthreads();
        if (jt + 2 <= jmax) {
            int nb = kvbuf + 2; if (nb >= 3) nb -= 3;
            load_kv(nb, (jt + 2) * 64);
        }
        CP_COMMIT();

        if (!qloaded) {
            #pragma unroll
            for (int kf = 0; kf < 4; ++kf) {
                const uint32_t addr = qhiS + (wm + (lane & 15)) * FP + kf * 32 + (lane >> 4) * 16;
                ldsm4(qah[kf][0], qah[kf][1], qah[kf][2], qah[kf][3], addr);
                ldsm4(qal[kf][0], qal[kf][1], qal[kf][2], qal[kf][3], addr + QARR);
            }
            qloaded = true;
        }

        const uint32_t khS = stS + kvbuf * KVSTG;
        const uint32_t vhS = khS + KVARR;
        if (++kvbuf == 3) kvbuf = 0;

        // ---- S = (Qh + Ql) @ Kh^T ----
        float s[8][4];
        #pragma unroll
        for (int i = 0; i < 8; ++i)
            #pragma unroll
            for (int e = 0; e < 4; ++e) s[i][e] = 0.f;

        #pragma unroll
        for (int kf = 0; kf < 4; ++kf) {
            uint32_t kb[4][4];
            #pragma unroll
            for (int ng = 0; ng < 4; ++ng) {
                const uint32_t addr = khS + (ng * 16 + (lane & 7) + ((lane >> 4) << 3)) * FP
                                      + kf * 32 + ((lane >> 3) & 1) * 16;
                ldsm4(kb[ng][0], kb[ng][1], kb[ng][2], kb[ng][3], addr);
            }
            #pragma unroll
            for (int ng = 0; ng < 4; ++ng)
                #pragma unroll
                for (int nf = 0; nf < 2; ++nf)
                    mma16816(s[ng * 2 + nf], qah[kf][0], qah[kf][1], qah[kf][2], qah[kf][3],
                             kb[ng][nf * 2], kb[ng][nf * 2 + 1]);
            #pragma unroll
            for (int ng = 0; ng < 4; ++ng)
                #pragma unroll
                for (int nf = 0; nf < 2; ++nf)
                    mma16816(s[ng * 2 + nf], qal[kf][0], qal[kf][1], qal[kf][2], qal[kf][3],
                             kb[ng][nf * 2], kb[ng][nf * 2 + 1]);
        }

        // ---- causal mask ----
        const int gr0 = q0 + wm + (lane >> 2);
        if (j0 + 64 > q0 + wm) {
            #pragma unroll
            for (int ni = 0; ni < 8; ++ni)
                #pragma unroll
                for (int e = 0; e < 4; ++e) {
                    const int col = j0 + ni * 8 + (lane & 3) * 2 + (e & 1);
                    const int row = gr0 + (e >> 1) * 8;
                    if (col > row) s[ni][e] = -1e30f;
                }
        }

        // ---- online softmax ----
        float rm0 = -1e30f, rm1 = -1e30f;
        #pragma unroll
        for (int ni = 0; ni < 8; ++ni) {
            rm0 = fmaxf(rm0, fmaxf(s[ni][0], s[ni][1]));
            rm1 = fmaxf(rm1, fmaxf(s[ni][2], s[ni][3]));
        }
        rm0 = fmaxf(rm0, __shfl_xor_sync(0xffffffffu, rm0, 1));
        rm0 = fmaxf(rm0, __shfl_xor_sync(0xffffffffu, rm0, 2));
        rm1 = fmaxf(rm1, __shfl_xor_sync(0xffffffffu, rm1, 1));
        rm1 = fmaxf(rm1, __shfl_xor_sync(0xffffffffu, rm1, 2));

        const float mn0 = fmaxf(m0, rm0), mn1 = fmaxf(m1, rm1);
        const float a0 = __expf(m0 - mn0), a1 = __expf(m1 - mn1);
        m0 = mn0; m1 = mn1;

        float rs0 = 0.f, rs1 = 0.f;
        #pragma unroll
        for (int ni = 0; ni < 8; ++ni) {
            s[ni][0] = __expf(s[ni][0] - mn0); rs0 += s[ni][0];
            s[ni][1] = __expf(s[ni][1] - mn0); rs0 += s[ni][1];
            s[ni][2] = __expf(s[ni][2] - mn1); rs1 += s[ni][2];
            s[ni][3] = __expf(s[ni][3] - mn1); rs1 += s[ni][3];
        }
        rs0 += __shfl_xor_sync(0xffffffffu, rs0, 1);
        rs0 += __shfl_xor_sync(0xffffffffu, rs0, 2);
        rs1 += __shfl_xor_sync(0xffffffffu, rs1, 1);
        rs1 += __shfl_xor_sync(0xffffffffu, rs1, 2);
        l0 = l0 * a0 + rs0;
        l1 = l1 * a1 + rs1;

        #pragma unroll
        for (int ni = 0; ni < 8; ++ni) {
            oAcc[ni][0] *= a0; oAcc[ni][1] *= a0;
            oAcc[ni][2] *= a1; oAcc[ni][3] *= a1;
        }

        // ---- P -> fp16 hi/lo A-fragments (register-only) ----
        uint32_t pah[4][4], pal[4][4];
        #pragma unroll
        for (int kf = 0; kf < 4; ++kf) {
            pah[kf][0] = packsplit(s[2 * kf][0],     s[2 * kf][1],     pal[kf][0]);
            pah[kf][1] = packsplit(s[2 * kf][2],     s[2 * kf][3],     pal[kf][1]);
            pah[kf][2] = packsplit(s[2 * kf + 1][0], s[2 * kf + 1][1], pal[kf][2]);
            pah[kf][3] = packsplit(s[2 * kf + 1][2], s[2 * kf + 1][3], pal[kf][3]);
        }

        // ---- O += (Ph + Pl) @ Vh ----
        #pragma unroll
        for (int kf = 0; kf < 4; ++kf) {
            uint32_t vb[4][4];
            #pragma unroll
            for (int ng = 0; ng < 4; ++ng) {
                const uint32_t addr = vhS + (kf * 16 + (lane & 15)) * FP
                                      + ng * 32 + (lane >> 4) * 16;
                ldsm4t(vb[ng][0], vb[ng][1], vb[ng][2], vb[ng][3], addr);
            }
            #pragma unroll
            for (int ng = 0; ng < 4; ++ng)
                #pragma unroll
                for (int nf = 0; nf < 2; ++nf)
                    mma16816(oAcc[ng * 2 + nf], pah[kf][0], pah[kf][1], pah[kf][2], pah[kf][3],
                             vb[ng][nf * 2], vb[ng][nf * 2 + 1]);
            #pragma unroll
            for (int ng = 0; ng < 4; ++ng)
                #pragma unroll
                for (int nf = 0; nf < 2; ++nf)
                    mma16816(oAcc[ng * 2 + nf], pal[kf][0], pal[kf][1], pal[kf][2], pal[kf][3],
                             vb[ng][nf * 2], vb[ng][nf * 2 + 1]);
        }
        // no trailing sync: 3-stage ring + top-of-loop barrier covers reuse
    }

    // ---- epilogue: normalize, split to fp16 hi/lo for output projection ----
    const float inv0 = 1.0f / l0, inv1 = 1.0f / l1;
    const int r0 = q0 + wm + (lane >> 2);
    #pragma unroll
    for (int ni = 0; ni < 8; ++ni) {
        const int col = h * DK + ni * 8 + (lane & 3) * 2;
        uint32_t lo;
        uint32_t hi = packsplit(oAcc[ni][0] * inv0, oAcc[ni][1] * inv0, lo);
        size_t idx = ((size_t)b * N + r0) * HD + col;
        *reinterpret_cast<uint32_t*>(g_AThi + idx) = hi;
        *reinterpret_cast<uint32_t*>(g_ATlo + idx) = lo;
        hi = packsplit(oAcc[ni][2] * inv1, oAcc[ni][3] * inv1, lo);
        idx = ((size_t)b * N + r0 + 8) * HD + col;
        *reinterpret_cast<uint32_t*>(g_AThi + idx) = hi;
        *reinterpret_cast<uint32_t*>(g_ATlo + idx) = lo;
    }
}

// ---------------------------------------------------------------------------
extern "C" void kernel_launch(void* const* d_in, const int* in_sizes, int n_in,
                              void* d_out, int out_size) {
    const float* X  = (const float*)d_in[0];
    // d_in[1] = mask (pure causal -> applied analytically)
    const float* Wq = (const float*)d_in[2];
    const float* Wk = (const float*)d_in[3];
    const float* Wv = (const float*)d_in[4];
    const float* Wo = (const float*)d_in[5];
    float* out = (float*)d_out;

    cudaFuncSetAttribute(qkv_mma,   cudaFuncAttributeMaxDynamicSharedMemorySize, GSMEM);
    cudaFuncSetAttribute(out_mma,   cudaFuncAttributeMaxDynamicSharedMemorySize, GSMEM);
    cudaFuncSetAttribute(flash_mma, cudaFuncAttributeMaxDynamicSharedMemorySize, FSMEM);

    // 0) conversions
    convX<<<(B * N * D / 2) / 256, 256>>>(X);
    convW<<<dim3(D / 32, HD / 32, 4), dim3(32, 8)>>>(Wq, Wk, Wv, Wo);

    // 1) QKV projections (2-product, X-corrected)
    qkv_mma<<<dim3(HD / 128, (B * N) / 128, 3), 256, GSMEM>>>();   // (8, 64, 3)

    // 2) causal flash attention (S and PV both 2-product — R11 config)
    flash_mma<<<dim3(N / 128, B * H), 256, FSMEM>>>();             // (16, 64)

    // 3) output projection (2-product, AT-corrected)
    out_mma<<<dim3(HD / 128, (B * N) / 128), 256, GSMEM>>>(out);   // (8, 64)
}

// round 14
// speedup vs baseline: 1.4083x; 1.1031x over previous
#include <cuda_runtime.h>
#include <cuda_fp16.h>
#include <cstdint>
#include <math.h>

// Problem constants
constexpr int B  = 4;
constexpr int N  = 2048;
constexpr int D  = 1024;
constexpr int H  = 16;
constexpr int DK = 64;
constexpr int HD = H * DK;   // 1024

// ---------------------------------------------------------------------------
// Scratch (device globals — no allocation allowed). fp16 storage.
// Q keeps a lo array (feeds logits); K/V pure fp16 (storage-quant bound).
// ---------------------------------------------------------------------------
__device__ __half g_Qhi[(size_t)B * H * N * DK];  // [bh][n][dk], pre-scaled 0.125
__device__ __half g_Qlo[(size_t)B * H * N * DK];
__device__ __half g_Khi[(size_t)B * H * N * DK];
__device__ __half g_Vhi[(size_t)B * H * N * DK];
__device__ __half g_Xhi[(size_t)B * N * D];       // X split, [m][k]
__device__ __half g_Xlo[(size_t)B * N * D];
__device__ __half g_WThi[4][(size_t)D * HD];      // W^T fp16, [n][k] (0=q,1=k,2=v,3=o)
__device__ __half g_AThi[(size_t)B * N * HD];     // attention out split, [m][k]
__device__ __half g_ATlo[(size_t)B * N * HD];

// ---------------------------------------------------------------------------
// PTX helpers (generic sm_80+ path — harness PTX targets compute_103, which
// rejects tcgen05/'a'-suffix features; legacy HMMA/ldmatrix/cp.async only)
// ---------------------------------------------------------------------------
__device__ __forceinline__ uint32_t smem_u32(const void* p) {
    uint32_t a;
    asm("{ .reg .u64 t; cvta.to.shared.u64 t, %1; cvt.u32.u64 %0, t; }" : "=r"(a) : "l"(p));
    return a;
}
__device__ __forceinline__ void cp16(uint32_t dst, const void* src) {
    asm volatile("cp.async.cg.shared.global [%0], [%1], 16;" :: "r"(dst), "l"(src));
}
#define CP_COMMIT() asm volatile("cp.async.commit_group;" ::: "memory")
#define CP_WAIT(n)  asm volatile("cp.async.wait_group %0;" :: "n"(n) : "memory")

__device__ __forceinline__ void ldsm4(uint32_t& r0, uint32_t& r1, uint32_t& r2, uint32_t& r3,
                                      uint32_t addr) {
    asm volatile("ldmatrix.sync.aligned.m8n8.x4.shared.b16 {%0,%1,%2,%3}, [%4];"
                 : "=r"(r0), "=r"(r1), "=r"(r2), "=r"(r3) : "r"(addr));
}
__device__ __forceinline__ void ldsm4t(uint32_t& r0, uint32_t& r1, uint32_t& r2, uint32_t& r3,
                                       uint32_t addr) {
    asm volatile("ldmatrix.sync.aligned.m8n8.x4.trans.shared.b16 {%0,%1,%2,%3}, [%4];"
                 : "=r"(r0), "=r"(r1), "=r"(r2), "=r"(r3) : "r"(addr));
}
// fp16 inputs, fp32 accumulate
__device__ __forceinline__ void mma16816(float* c,
                                         uint32_t a0, uint32_t a1, uint32_t a2, uint32_t a3,
                                         uint32_t b0, uint32_t b1) {
    asm volatile("mma.sync.aligned.m16n8k16.row.col.f32.f16.f16.f32 "
                 "{%0,%1,%2,%3}, {%4,%5,%6,%7}, {%8,%9}, {%0,%1,%2,%3};"
                 : "+f"(c[0]), "+f"(c[1]), "+f"(c[2]), "+f"(c[3])
                 : "r"(a0), "r"(a1), "r"(a2), "r"(a3), "r"(b0), "r"(b1));
}
// split v0,v1 into packed fp16 hi pair (return) and lo pair (out param)
__device__ __forceinline__ uint32_t packsplit(float v0, float v1, uint32_t& lo) {
    const __half h0 = __float2half_rn(v0);
    const __half h1 = __float2half_rn(v1);
    __half2 hp; hp.x = h0; hp.y = h1;
    __half2 lp;
    lp.x = __float2half_rn(v0 - __half2float(h0));
    lp.y = __float2half_rn(v1 - __half2float(h1));
    lo = *reinterpret_cast<uint32_t*>(&lp);
    return *reinterpret_cast<uint32_t*>(&hp);
}
__device__ __forceinline__ uint32_t packh2(float v0, float v1) {
    __half2 hp; hp.x = __float2half_rn(v0); hp.y = __float2half_rn(v1);
    return *reinterpret_cast<uint32_t*>(&hp);
}

// ---------------------------------------------------------------------------
// fp16 2-product HMMA GEMM body, 128x256 CTA tile:
//   C[128,256] = (Ah + Al) @ Bh,  B given as B^T [n][k] fp16.
// Wider N-tile halves the per-output A-load redundancy so the cp.async issue
// stream (2048 cp16/chunk for TWO tiles) balances the doubled MMA stream —
// the 128x128 version was partially LDGSTS-issue-bound.
// 8 warps as 2m x 4n (warp tile 64x64). 4-stage cp.async ring, one
// __syncthreads per K-chunk. f32 accumulate.
// ---------------------------------------------------------------------------
constexpr int APITCH_B = 80;
constexpr int SROWS    = 512;                  // Ah(128) | Al(128) | B(256)
constexpr int AL_OFF   = 128 * APITCH_B;       // 10240
constexpr int B_OFF    = 256 * APITCH_B;       // 20480
constexpr int STAGE_B  = SROWS * APITCH_B;     // 40960
constexpr int GSMEM    = 4 * STAGE_B;          // 163840

__device__ __forceinline__ void gemm_mma_body(
    const __half* __restrict__ Ahi, const __half* __restrict__ Alo,
    const __half* __restrict__ Bhi,
    int rowBase, int colBase, char* sm, float acc[4][8][4])
{
    const int tid  = threadIdx.x;
    const int lane = tid & 31;
    const int w    = tid >> 5;
    const int wm   = (w >> 2) * 64;    // warp m offset (0 or 64)
    const int wn   = (w & 3) * 64;     // warp n offset (0..192)
    const uint32_t sb = smem_u32(sm);

    auto load_stage = [&](int s, int k0) {
        const uint32_t base = sb + s * STAGE_B;
        #pragma unroll
        for (int t = 0; t < 8; ++t) {          // t-major: 4 lanes = 64B row segment
            const int idx = t * 256 + tid;     // 0..2047
            const int r = idx >> 2, ch = idx & 3;
            const __half* src;
            int grow;
            if (t < 2)      { src = Ahi; grow = rowBase + r; }
            else if (t < 4) { src = Alo; grow = rowBase + r - 128; }
            else            { src = Bhi; grow = colBase + r - 256; }
            cp16(base + r * APITCH_B + ch * 16,
                 src + (size_t)grow * D + k0 + ch * 8);
        }
    };

    auto comp = [&](int s) {
        const uint32_t base = sb + s * STAGE_B;
        #pragma unroll
        for (int k16 = 0; k16 < 2; ++k16) {
            uint32_t Ah[4][4], Al[4][4];
            #pragma unroll
            for (int mi = 0; mi < 4; ++mi) {
                const uint32_t addr = base + (wm + mi * 16 + (lane & 15)) * APITCH_B
                                      + k16 * 32 + (lane >> 4) * 16;
                ldsm4(Ah[mi][0], Ah[mi][1], Ah[mi][2], Ah[mi][3], addr);
                ldsm4(Al[mi][0], Al[mi][1], Al[mi][2], Al[mi][3], addr + AL_OFF);
            }
            #pragma unroll
            for (int np = 0; np < 4; ++np) {   // 4 groups of 16 B-rows (=2 nf frags)
                uint32_t Bh[4];
                const int nrow = wn + np * 16 + (lane & 7) + ((lane >> 4) << 3);
                const uint32_t addr = base + B_OFF + nrow * APITCH_B
                                      + k16 * 32 + ((lane >> 3) & 1) * 16;
                ldsm4(Bh[0], Bh[1], Bh[2], Bh[3], addr);
                // Ah*Bh: 8 independent accs
                #pragma unroll
                for (int mi = 0; mi < 4; ++mi)
                    #pragma unroll
                    for (int h2 = 0; h2 < 2; ++h2)
                        mma16816(acc[mi][np * 2 + h2],
                                 Ah[mi][0], Ah[mi][1], Ah[mi][2], Ah[mi][3],
                                 Bh[h2 * 2], Bh[h2 * 2 + 1]);
                // Al*Bh
                #pragma unroll
                for (int mi = 0; mi < 4; ++mi)
                    #pragma unroll
                    for (int h2 = 0; h2 < 2; ++h2)
                        mma16816(acc[mi][np * 2 + h2],
                                 Al[mi][0], Al[mi][1], Al[mi][2], Al[mi][3],
                                 Bh[h2 * 2], Bh[h2 * 2 + 1]);
            }
        }
    };

    constexpr int NC = D / 32;   // 32 chunks
    load_stage(0, 0);            CP_COMMIT();
    load_stage(1, 32);           CP_COMMIT();
    load_stage(2, 64);           CP_COMMIT();
    for (int c = 0; c < NC; ++c) {
        CP_WAIT(2);
        __syncthreads();
        if (c + 3 < NC) load_stage((c + 3) & 3, (c + 3) * 32);
        CP_COMMIT();
        comp(c & 3);
    }
}

// QKV projection (2-product, X-corrected). z=0: Q hi+lo pre-scaled; z=1,2: fp16.
__global__ __launch_bounds__(256, 1) void qkv_mma() {
    extern __shared__ char sm[];
    const int z = blockIdx.z;
    const int rowBase = blockIdx.y * 128, colBase = blockIdx.x * 256;
    float acc[4][8][4];
    #pragma unroll
    for (int i = 0; i < 4; ++i)
        #pragma unroll
        for (int j = 0; j < 8; ++j)
            #pragma unroll
            for (int k = 0; k < 4; ++k) acc[i][j][k] = 0.f;

    gemm_mma_body(g_Xhi, g_Xlo, g_WThi[z], rowBase, colBase, sm, acc);

    const int lane = threadIdx.x & 31, w = threadIdx.x >> 5;
    const int wm = (w >> 2) * 64, wn = (w & 3) * 64;
    #pragma unroll
    for (int mi = 0; mi < 4; ++mi)
        #pragma unroll
        for (int nf = 0; nf < 8; ++nf) {
            const int r0 = rowBase + wm + mi * 16 + (lane >> 2);
            const int c0 = colBase + wn + nf * 8 + (lane & 3) * 2;
            const int hh = c0 >> 6, dd = c0 & 63;
            #pragma unroll
            for (int rr = 0; rr < 2; ++rr) {
                const int r = r0 + rr * 8;
                const int b = r >> 11, n = r & (N - 1);
                const size_t idx = (((size_t)(b * H + hh)) * N + n) * DK + dd;
                const float v0 = acc[mi][nf][rr * 2], v1 = acc[mi][nf][rr * 2 + 1];
                if (z == 0) {
                    uint32_t lo;
                    const uint32_t hi = packsplit(v0 * 0.125f, v1 * 0.125f, lo);
                    *reinterpret_cast<uint32_t*>(g_Qhi + idx) = hi;
                    *reinterpret_cast<uint32_t*>(g_Qlo + idx) = lo;
                } else {
                    __half* Ohi = (z == 1) ? g_Khi : g_Vhi;
                    *reinterpret_cast<uint32_t*>(Ohi + idx) = packh2(v0, v1);
                }
            }
        }
}

// Output projection (2-product, AT-corrected): (AThi + ATlo) @ Wo -> fp32
__global__ __launch_bounds__(256, 1) void out_mma(float* __restrict__ Cout) {
    extern __shared__ char sm[];
    const int rowBase = blockIdx.y * 128, colBase = blockIdx.x * 256;
    float acc[4][8][4];
    #pragma unroll
    for (int i = 0; i < 4; ++i)
        #pragma unroll
        for (int j = 0; j < 8; ++j)
            #pragma unroll
            for (int k = 0; k < 4; ++k) acc[i][j][k] = 0.f;

    gemm_mma_body(g_AThi, g_ATlo, g_WThi[3], rowBase, colBase, sm, acc);

    const int lane = threadIdx.x & 31, w = threadIdx.x >> 5;
    const int wm = (w >> 2) * 64, wn = (w & 3) * 64;
    #pragma unroll
    for (int mi = 0; mi < 4; ++mi)
        #pragma unroll
        for (int nf = 0; nf < 8; ++nf) {
            const int r0 = rowBase + wm + mi * 16 + (lane >> 2);
            const int c0 = colBase + wn + nf * 8 + (lane & 3) * 2;
            #pragma unroll
            for (int e = 0; e < 4; ++e)
                Cout[(size_t)(r0 + (e >> 1) * 8) * HD + c0 + (e & 1)] = acc[mi][nf][e];
        }
}

// ---------------------------------------------------------------------------
// Precision-split conversion passes
// ---------------------------------------------------------------------------
__global__ void convX(const float* __restrict__ X) {
    const size_t i = ((size_t)blockIdx.x * 256 + threadIdx.x) * 2;
    const float2 v = *(const float2*)(X + i);
    uint32_t lo;
    const uint32_t hi = packsplit(v.x, v.y, lo);
    *reinterpret_cast<uint32_t*>(g_Xhi + i) = hi;
    *reinterpret_cast<uint32_t*>(g_Xlo + i) = lo;
}

// Transpose W -> WT[n][k], fp16 (hi only)
__global__ void convW(const float* __restrict__ Wq, const float* __restrict__ Wk,
                      const float* __restrict__ Wv, const float* __restrict__ Wo) {
    const int z = blockIdx.z;
    const float* W = (z == 0) ? Wq : (z == 1) ? Wk : (z == 2) ? Wv : Wo;
    __half* Th = g_WThi[z];
    __shared__ float t[32][33];
    const int k0 = blockIdx.x * 32, n0 = blockIdx.y * 32;
    #pragma unroll
    for (int j = 0; j < 32; j += 8)
        t[threadIdx.y + j][threadIdx.x] = W[(size_t)(k0 + threadIdx.y + j) * HD + n0 + threadIdx.x];
    __syncthreads();
    #pragma unroll
    for (int j = 0; j < 32; j += 8) {
        const int n = n0 + threadIdx.y + j, k = k0 + threadIdx.x;
        Th[(size_t)n * D + k] = __float2half_rn(t[threadIdx.x][threadIdx.y + j]);
    }
}

// ---------------------------------------------------------------------------
// Tensor-core flash attention (causal) — proven 241 us config (R11/R13):
// S = Qh*Kh + Ql*Kh (2-product).  O = Ph*Vh + Pl*Vh (2-product).
// The 2-product PV is load-bearing for SPEED too: 1-product exposed
// trans-LDSM latency at 2 warps/SMSP (R12 regression).
// 128 q-rows per CTA, 8 warps. 3-stage KV ring (Kh|Vh), f32 acc.
// ---------------------------------------------------------------------------
constexpr int FP     = 144;            // smem pitch (128B data + 16B pad)
constexpr int KVARR  = 64 * FP;        // 9216
constexpr int KVSTG  = 2 * KVARR;      // Kh|Vh: 18432
constexpr int QARR   = 128 * FP;       // 18432
constexpr int FSTAGES = 3;
constexpr int FSMEM  = 2 * QARR + FSTAGES * KVSTG;   // 92160

__global__ __launch_bounds__(256, 1)
void flash_mma() {
    extern __shared__ char sm[];
    const uint32_t sb = smem_u32(sm);
    const int tid = threadIdx.x, lane = tid & 31, w = tid >> 5;
    const int bh = blockIdx.y;
    const int qt = gridDim.x - 1 - blockIdx.x;        // long blocks first
    const int q0 = qt * 128;
    const int b = bh >> 4, h = bh & (H - 1);
    const int wm = w * 16;

    const __half* Qh = g_Qhi + (size_t)bh * N * DK;
    const __half* Ql = g_Qlo + (size_t)bh * N * DK;
    const __half* Kh = g_Khi + (size_t)bh * N * DK;
    const __half* Vh = g_Vhi + (size_t)bh * N * DK;

    const uint32_t qhiS = sb, qloS = sb + QARR, stS = sb + 2 * QARR;

    auto load_kv = [&](int s, int j0) {
        const uint32_t base = stS + s * KVSTG;
        #pragma unroll
        for (int t = 0; t < 2; ++t) {
            const int i = tid + t * 256;
            const int r = i >> 3, ch = i & 7;
            const uint32_t off = r * FP + ch * 16;
            const size_t gi = (size_t)(j0 + r) * DK + ch * 8;
            cp16(base + off,         Kh + gi);
            cp16(base + KVARR + off, Vh + gi);
        }
    };

    const int jmax = 2 * qt + 1;

    for (int i = tid; i < 1024; i += 256) {
        const int r = i >> 3, ch = i & 7;
        const size_t gi = (size_t)(q0 + r) * DK + ch * 8;
        cp16(qhiS + r * FP + ch * 16, Qh + gi);
        cp16(qloS + r * FP + ch * 16, Ql + gi);
    }
    load_kv(0, 0);
    CP_COMMIT();
    load_kv(1, 64);
    CP_COMMIT();

    float m0 = -1e30f, m1 = -1e30f, l0 = 0.f, l1 = 0.f;
    float oAcc[8][4];
    #pragma unroll
    for (int i = 0; i < 8; ++i)
        #pragma unroll
        for (int e = 0; e < 4; ++e) oAcc[i][e] = 0.f;

    uint32_t qah[4][4], qal[4][4];
    bool qloaded = false;
    int kvbuf = 0;

    for (int jt = 0; jt <= jmax; ++jt) {
        const int j0 = jt * 64;
        CP_WAIT(1);
        __syncthreads();
        if (jt + 2 <= jmax) {
            int nb = kvbuf + 2; if (nb >= 3) nb -= 3;
            load_kv(nb, (jt + 2) * 64);
        }
        CP_COMMIT();

        if (!qloaded) {
            #pragma unroll
            for (int kf = 0; kf < 4; ++kf) {
                const uint32_t addr = qhiS + (wm + (lane & 15)) * FP + kf * 32 + (lane >> 4) * 16;
                ldsm4(qah[kf][0], qah[kf][1], qah[kf][2], qah[kf][3], addr);
                ldsm4(qal[kf][0], qal[kf][1], qal[kf][2], qal[kf][3], addr + QARR);
            }
            qloaded = true;
        }

        const uint32_t khS = stS + kvbuf * KVSTG;
        const uint32_t vhS = khS + KVARR;
        if (++kvbuf == 3) kvbuf = 0;

        // ---- S = (Qh + Ql) @ Kh^T ----
        float s[8][4];
        #pragma unroll
        for (int i = 0; i < 8; ++i)
            #pragma unroll
            for (int e = 0; e < 4; ++e) s[i][e] = 0.f;

        #pragma unroll
        for (int kf = 0; kf < 4; ++kf) {
            uint32_t kb[4][4];
            #pragma unroll
            for (int ng = 0; ng < 4; ++ng) {
                const uint32_t addr = khS + (ng * 16 + (lane & 7) + ((lane >> 4) << 3)) * FP
                                      + kf * 32 + ((lane >> 3) & 1) * 16;
                ldsm4(kb[ng][0], kb[ng][1], kb[ng][2], kb[ng][3], addr);
            }
            #pragma unroll
            for (int ng = 0; ng < 4; ++ng)
                #pragma unroll
                for (int nf = 0; nf < 2; ++nf)
                    mma16816(s[ng * 2 + nf], qah[kf][0], qah[kf][1], qah[kf][2], qah[kf][3],
                             kb[ng][nf * 2], kb[ng][nf * 2 + 1]);
            #pragma unroll
            for (int ng = 0; ng < 4; ++ng)
                #pragma unroll
                for (int nf = 0; nf < 2; ++nf)
                    mma16816(s[ng * 2 + nf], qal[kf][0], qal[kf][1], qal[kf][2], qal[kf][3],
                             kb[ng][nf * 2], kb[ng][nf * 2 + 1]);
        }

        // ---- causal mask ----
        const int gr0 = q0 + wm + (lane >> 2);
        if (j0 + 64 > q0 + wm) {
            #pragma unroll
            for (int ni = 0; ni < 8; ++ni)
                #pragma unroll
                for (int e = 0; e < 4; ++e) {
                    const int col = j0 + ni * 8 + (lane & 3) * 2 + (e & 1);
                    const int row = gr0 + (e >> 1) * 8;
                    if (col > row) s[ni][e] = -1e30f;
                }
        }

        // ---- online softmax ----
        float rm0 = -1e30f, rm1 = -1e30f;
        #pragma unroll
        for (int ni = 0; ni < 8; ++ni) {
            rm0 = fmaxf(rm0, fmaxf(s[ni][0], s[ni][1]));
            rm1 = fmaxf(rm1, fmaxf(s[ni][2], s[ni][3]));
        }
        rm0 = fmaxf(rm0, __shfl_xor_sync(0xffffffffu, rm0, 1));
        rm0 = fmaxf(rm0, __shfl_xor_sync(0xffffffffu, rm0, 2));
        rm1 = fmaxf(rm1, __shfl_xor_sync(0xffffffffu, rm1, 1));
        rm1 = fmaxf(rm1, __shfl_xor_sync(0xffffffffu, rm1, 2));

        const float mn0 = fmaxf(m0, rm0), mn1 = fmaxf(m1, rm1);
        const float a0 = __expf(m0 - mn0), a1 = __expf(m1 - mn1);
        m0 = mn0; m1 = mn1;

        float rs0 = 0.f, rs1 = 0.f;
        #pragma unroll
        for (int ni = 0; ni < 8; ++ni) {
            s[ni][0] = __expf(s[ni][0] - mn0); rs0 += s[ni][0];
            s[ni][1] = __expf(s[ni][1] - mn0); rs0 += s[ni][1];
            s[ni][2] = __expf(s[ni][2] - mn1); rs1 += s[ni][2];
            s[ni][3] = __expf(s[ni][3] - mn1); rs1 += s[ni][3];
        }
        rs0 += __shfl_xor_sync(0xffffffffu, rs0, 1);
        rs0 += __shfl_xor_sync(0xffffffffu, rs0, 2);
        rs1 += __shfl_xor_sync(0xffffffffu, rs1, 1);
        rs1 += __shfl_xor_sync(0xffffffffu, rs1, 2);
        l0 = l0 * a0 + rs0;
        l1 = l1 * a1 + rs1;

        #pragma unroll
        for (int ni = 0; ni < 8; ++ni) {
            oAcc[ni][0] *= a0; oAcc[ni][1] *= a0;
            oAcc[ni][2] *= a1; oAcc[ni][3] *= a1;
        }

        // ---- P -> fp16 hi/lo A-fragments (register-only) ----
        uint32_t pah[4][4], pal[4][4];
        #pragma unroll
        for (int kf = 0; kf < 4; ++kf) {
            pah[kf][0] = packsplit(s[2 * kf][0],     s[2 * kf][1],     pal[kf][0]);
            pah[kf][1] = packsplit(s[2 * kf][2],     s[2 * kf][3],     pal[kf][1]);
            pah[kf][2] = packsplit(s[2 * kf + 1][0], s[2 * kf + 1][1], pal[kf][2]);
            pah[kf][3] = packsplit(s[2 * kf + 1][2], s[2 * kf + 1][3], pal[kf][3]);
        }

        // ---- O += (Ph + Pl) @ Vh ----
        #pragma unroll
        for (int kf = 0; kf < 4; ++kf) {
            uint32_t vb[4][4];
            #pragma unroll
            for (int ng = 0; ng < 4; ++ng) {
                const uint32_t addr = vhS + (kf * 16 + (lane & 15)) * FP
                                      + ng * 32 + (lane >> 4) * 16;
                ldsm4t(vb[ng][0], vb[ng][1], vb[ng][2], vb[ng][3], addr);
            }
            #pragma unroll
            for (int ng = 0; ng < 4; ++ng)
                #pragma unroll
                for (int nf = 0; nf < 2; ++nf)
                    mma16816(oAcc[ng * 2 + nf], pah[kf][0], pah[kf][1], pah[kf][2], pah[kf][3],
                             vb[ng][nf * 2], vb[ng][nf * 2 + 1]);
            #pragma unroll
            for (int ng = 0; ng < 4; ++ng)
                #pragma unroll
                for (int nf = 0; nf < 2; ++nf)
                    mma16816(oAcc[ng * 2 + nf], pal[kf][0], pal[kf][1], pal[kf][2], pal[kf][3],
                             vb[ng][nf * 2], vb[ng][nf * 2 + 1]);
        }
        // no trailing sync: 3-stage ring + top-of-loop barrier covers reuse
    }

    // ---- epilogue: normalize, split to fp16 hi/lo for output projection ----
    const float inv0 = 1.0f / l0, inv1 = 1.0f / l1;
    const int r0 = q0 + wm + (lane >> 2);
    #pragma unroll
    for (int ni = 0; ni < 8; ++ni) {
        const int col = h * DK + ni * 8 + (lane & 3) * 2;
        uint32_t lo;
        uint32_t hi = packsplit(oAcc[ni][0] * inv0, oAcc[ni][1] * inv0, lo);
        size_t idx = ((size_t)b * N + r0) * HD + col;
        *reinterpret_cast<uint32_t*>(g_AThi + idx) = hi;
        *reinterpret_cast<uint32_t*>(g_ATlo + idx) = lo;
        hi = packsplit(oAcc[ni][2] * inv1, oAcc[ni][3] * inv1, lo);
        idx = ((size_t)b * N + r0 + 8) * HD + col;
        *reinterpret_cast<uint32_t*>(g_AThi + idx) = hi;
        *reinterpret_cast<uint32_t*>(g_ATlo + idx) = lo;
    }
}

// ---------------------------------------------------------------------------
extern "C" void kernel_launch(void* const* d_in, const int* in_sizes, int n_in,
                              void* d_out, int out_size) {
    const float* X  = (const float*)d_in[0];
    // d_in[1] = mask (pure causal -> applied analytically)
    const float* Wq = (const float*)d_in[2];
    const float* Wk = (const float*)d_in[3];
    const float* Wv = (const float*)d_in[4];
    const float* Wo = (const float*)d_in[5];
    float* out = (float*)d_out;

    cudaFuncSetAttribute(qkv_mma,   cudaFuncAttributeMaxDynamicSharedMemorySize, GSMEM);
    cudaFuncSetAttribute(out_mma,   cudaFuncAttributeMaxDynamicSharedMemorySize, GSMEM);
    cudaFuncSetAttribute(flash_mma, cudaFuncAttributeMaxDynamicSharedMemorySize, FSMEM);

    // 0) conversions
    convX<<<(B * N * D / 2) / 256, 256>>>(X);
    convW<<<dim3(D / 32, HD / 32, 4), dim3(32, 8)>>>(Wq, Wk, Wv, Wo);

    // 1) QKV projections (2-product, 128x256 tiles)
    qkv_mma<<<dim3(HD / 256, (B * N) / 128, 3), 256, GSMEM>>>();   // (4, 64, 3)

    // 2) causal flash attention (proven 241us config)
    flash_mma<<<dim3(N / 128, B * H), 256, FSMEM>>>();             // (16, 64)

    // 3) output projection (2-product, 128x256 tiles)
    out_mma<<<dim3(HD / 256, (B * N) / 128), 256, GSMEM>>>(out);   // (4, 64)
}

// round 15
// speedup vs baseline: 1.7914x; 1.2720x over previous
#include <cuda_runtime.h>
#include <cuda_fp16.h>
#include <cstdint>
#include <math.h>

// Problem constants
constexpr int B  = 4;
constexpr int N  = 2048;
constexpr int D  = 1024;
constexpr int H  = 16;
constexpr int DK = 64;
constexpr int HD = H * DK;   // 1024

// ---------------------------------------------------------------------------
// Scratch (device globals — no allocation allowed). fp16 storage.
// Q/K/V pure fp16 (storage/GEMM quantization accepted, calibrated ~2e-4/term).
// AT keeps hi/lo (out projection stays A-corrected).
// ---------------------------------------------------------------------------
__device__ __half g_Qhi[(size_t)B * H * N * DK];  // [bh][n][dk], pre-scaled 0.125
__device__ __half g_Khi[(size_t)B * H * N * DK];
__device__ __half g_Vhi[(size_t)B * H * N * DK];
__device__ __half g_Xhi[(size_t)B * N * D];       // X fp16, [m][k]
__device__ __half g_WThi[4][(size_t)D * HD];      // W^T fp16, [n][k] (0=q,1=k,2=v,3=o)
__device__ __half g_AThi[(size_t)B * N * HD];     // attention out split, [m][k]
__device__ __half g_ATlo[(size_t)B * N * HD];

// ---------------------------------------------------------------------------
// PTX helpers (generic sm_80+ path — harness PTX targets compute_103, which
// rejects tcgen05/'a'-suffix features; legacy HMMA/ldmatrix/cp.async only)
// ---------------------------------------------------------------------------
__device__ __forceinline__ uint32_t smem_u32(const void* p) {
    uint32_t a;
    asm("{ .reg .u64 t; cvta.to.shared.u64 t, %1; cvt.u32.u64 %0, t; }" : "=r"(a) : "l"(p));
    return a;
}
__device__ __forceinline__ void cp16(uint32_t dst, const void* src) {
    asm volatile("cp.async.cg.shared.global [%0], [%1], 16;" :: "r"(dst), "l"(src));
}
#define CP_COMMIT() asm volatile("cp.async.commit_group;" ::: "memory")
#define CP_WAIT(n)  asm volatile("cp.async.wait_group %0;" :: "n"(n) : "memory")

__device__ __forceinline__ void ldsm4(uint32_t& r0, uint32_t& r1, uint32_t& r2, uint32_t& r3,
                                      uint32_t addr) {
    asm volatile("ldmatrix.sync.aligned.m8n8.x4.shared.b16 {%0,%1,%2,%3}, [%4];"
                 : "=r"(r0), "=r"(r1), "=r"(r2), "=r"(r3) : "r"(addr));
}
__device__ __forceinline__ void ldsm4t(uint32_t& r0, uint32_t& r1, uint32_t& r2, uint32_t& r3,
                                       uint32_t addr) {
    asm volatile("ldmatrix.sync.aligned.m8n8.x4.trans.shared.b16 {%0,%1,%2,%3}, [%4];"
                 : "=r"(r0), "=r"(r1), "=r"(r2), "=r"(r3) : "r"(addr));
}
// fp16 inputs, fp32 accumulate
__device__ __forceinline__ void mma16816(float* c,
                                         uint32_t a0, uint32_t a1, uint32_t a2, uint32_t a3,
                                         uint32_t b0, uint32_t b1) {
    asm volatile("mma.sync.aligned.m16n8k16.row.col.f32.f16.f16.f32 "
                 "{%0,%1,%2,%3}, {%4,%5,%6,%7}, {%8,%9}, {%0,%1,%2,%3};"
                 : "+f"(c[0]), "+f"(c[1]), "+f"(c[2]), "+f"(c[3])
                 : "r"(a0), "r"(a1), "r"(a2), "r"(a3), "r"(b0), "r"(b1));
}
// split v0,v1 into packed fp16 hi pair (return) and lo pair (out param)
__device__ __forceinline__ uint32_t packsplit(float v0, float v1, uint32_t& lo) {
    const __half h0 = __float2half_rn(v0);
    const __half h1 = __float2half_rn(v1);
    __half2 hp; hp.x = h0; hp.y = h1;
    __half2 lp;
    lp.x = __float2half_rn(v0 - __half2float(h0));
    lp.y = __float2half_rn(v1 - __half2float(h1));
    lo = *reinterpret_cast<uint32_t*>(&lp);
    return *reinterpret_cast<uint32_t*>(&hp);
}
__device__ __forceinline__ uint32_t packh2(float v0, float v1) {
    __half2 hp; hp.x = __float2half_rn(v0); hp.y = __float2half_rn(v1);
    return *reinterpret_cast<uint32_t*>(&hp);
}

// ---------------------------------------------------------------------------
// fp16 HMMA GEMM body, 128x256 CTA tile: C = (Ah [+ Al]) @ Bh.
// USE_AL=1 (2-product): loads 512 rows/chunk — MMA-bound (4096 vs 4096 cyc).
// USE_AL=0 (1-product): loads 384 rows/chunk — load-bound at 3072 cyc,
//   a 25% win over the 2-product chunk (valid ONLY at this wide tile; at
//   128x128 the 1-product was load-bound with no gain — R12 measured).
// 8 warps as 2m x 4n (warp tile 64x64). 4-stage cp.async ring, one
// __syncthreads per K-chunk. f32 accumulate.
// ---------------------------------------------------------------------------
constexpr int APITCH_B = 80;

template <bool USE_AL>
__device__ __forceinline__ void gemm_mma_body(
    const __half* __restrict__ Ahi, const __half* __restrict__ Alo,
    const __half* __restrict__ Bhi,
    int rowBase, int colBase, char* sm, float acc[4][8][4])
{
    constexpr int SROWS   = USE_AL ? 512 : 384;       // Ah(128) [| Al(128)] | B(256)
    constexpr int AL_OFF  = 128 * APITCH_B;
    constexpr int B_OFF   = (USE_AL ? 256 : 128) * APITCH_B;
    constexpr int STAGE_B = SROWS * APITCH_B;
    constexpr int NT      = SROWS / 64;               // cp16 rounds (8 or 6)

    const int tid  = threadIdx.x;
    const int lane = tid & 31;
    const int w    = tid >> 5;
    const int wm   = (w >> 2) * 64;
    const int wn   = (w & 3) * 64;
    const uint32_t sb = smem_u32(sm);

    auto load_stage = [&](int s, int k0) {
        const uint32_t base = sb + s * STAGE_B;
        #pragma unroll
        for (int t = 0; t < NT; ++t) {
            const int idx = t * 256 + tid;
            const int r = idx >> 2, ch = idx & 3;
            const __half* src;
            int grow;
            if (r < 128)                 { src = Ahi; grow = rowBase + r; }
            else if (USE_AL && r < 256)  { src = Alo; grow = rowBase + r - 128; }
            else                         { src = Bhi; grow = colBase + r - (USE_AL ? 256 : 128); }
            cp16(base + r * APITCH_B + ch * 16,
                 src + (size_t)grow * D + k0 + ch * 8);
        }
    };

    auto comp = [&](int s) {
        const uint32_t base = sb + s * STAGE_B;
        #pragma unroll
        for (int k16 = 0; k16 < 2; ++k16) {
            uint32_t Ah[4][4], Al[4][4];
            #pragma unroll
            for (int mi = 0; mi < 4; ++mi) {
                const uint32_t addr = base + (wm + mi * 16 + (lane & 15)) * APITCH_B
                                      + k16 * 32 + (lane >> 4) * 16;
                ldsm4(Ah[mi][0], Ah[mi][1], Ah[mi][2], Ah[mi][3], addr);
                if (USE_AL)
                    ldsm4(Al[mi][0], Al[mi][1], Al[mi][2], Al[mi][3], addr + AL_OFF);
            }
            #pragma unroll
            for (int np = 0; np < 4; ++np) {
                uint32_t Bh[4];
                const int nrow = wn + np * 16 + (lane & 7) + ((lane >> 4) << 3);
                const uint32_t addr = base + B_OFF + nrow * APITCH_B
                                      + k16 * 32 + ((lane >> 3) & 1) * 16;
                ldsm4(Bh[0], Bh[1], Bh[2], Bh[3], addr);
                #pragma unroll
                for (int mi = 0; mi < 4; ++mi)
                    #pragma unroll
                    for (int h2 = 0; h2 < 2; ++h2)
                        mma16816(acc[mi][np * 2 + h2],
                                 Ah[mi][0], Ah[mi][1], Ah[mi][2], Ah[mi][3],
                                 Bh[h2 * 2], Bh[h2 * 2 + 1]);
                if (USE_AL) {
                    #pragma unroll
                    for (int mi = 0; mi < 4; ++mi)
                        #pragma unroll
                        for (int h2 = 0; h2 < 2; ++h2)
                            mma16816(acc[mi][np * 2 + h2],
                                     Al[mi][0], Al[mi][1], Al[mi][2], Al[mi][3],
                                     Bh[h2 * 2], Bh[h2 * 2 + 1]);
                }
            }
        }
    };

    constexpr int NC = D / 32;   // 32 chunks
    load_stage(0, 0);            CP_COMMIT();
    load_stage(1, 32);           CP_COMMIT();
    load_stage(2, 64);           CP_COMMIT();
    for (int c = 0; c < NC; ++c) {
        CP_WAIT(2);
        __syncthreads();
        if (c + 3 < NC) load_stage((c + 3) & 3, (c + 3) * 32);
        CP_COMMIT();
        comp(c & 3);
    }
}

constexpr int GSMEM_QKV = 4 * 384 * APITCH_B;   // 122880
constexpr int GSMEM_OUT = 4 * 512 * APITCH_B;   // 163840

// QKV projection (1-product fp16, 128x256 tiles). Epilogue: Q pre-scaled.
__global__ __launch_bounds__(256, 1) void qkv_mma() {
    extern __shared__ char sm[];
    const int z = blockIdx.z;
    const int rowBase = blockIdx.y * 128, colBase = blockIdx.x * 256;
    float acc[4][8][4];
    #pragma unroll
    for (int i = 0; i < 4; ++i)
        #pragma unroll
        for (int j = 0; j < 8; ++j)
            #pragma unroll
            for (int k = 0; k < 4; ++k) acc[i][j][k] = 0.f;

    gemm_mma_body<false>(g_Xhi, nullptr, g_WThi[z], rowBase, colBase, sm, acc);

    __half* Out = (z == 0) ? g_Qhi : (z == 1) ? g_Khi : g_Vhi;
    const float scale = (z == 0) ? 0.125f : 1.0f;
    const int lane = threadIdx.x & 31, w = threadIdx.x >> 5;
    const int wm = (w >> 2) * 64, wn = (w & 3) * 64;
    #pragma unroll
    for (int mi = 0; mi < 4; ++mi)
        #pragma unroll
        for (int nf = 0; nf < 8; ++nf) {
            const int r0 = rowBase + wm + mi * 16 + (lane >> 2);
            const int c0 = colBase + wn + nf * 8 + (lane & 3) * 2;
            const int hh = c0 >> 6, dd = c0 & 63;
            #pragma unroll
            for (int rr = 0; rr < 2; ++rr) {
                const int r = r0 + rr * 8;
                const int b = r >> 11, n = r & (N - 1);
                const size_t idx = (((size_t)(b * H + hh)) * N + n) * DK + dd;
                *reinterpret_cast<uint32_t*>(Out + idx) =
                    packh2(acc[mi][nf][rr * 2] * scale, acc[mi][nf][rr * 2 + 1] * scale);
            }
        }
}

// Output projection (2-product, AT-corrected): (AThi + ATlo) @ Wo -> fp32
__global__ __launch_bounds__(256, 1) void out_mma(float* __restrict__ Cout) {
    extern __shared__ char sm[];
    const int rowBase = blockIdx.y * 128, colBase = blockIdx.x * 256;
    float acc[4][8][4];
    #pragma unroll
    for (int i = 0; i < 4; ++i)
        #pragma unroll
        for (int j = 0; j < 8; ++j)
            #pragma unroll
            for (int k = 0; k < 4; ++k) acc[i][j][k] = 0.f;

    gemm_mma_body<true>(g_AThi, g_ATlo, g_WThi[3], rowBase, colBase, sm, acc);

    const int lane = threadIdx.x & 31, w = threadIdx.x >> 5;
    const int wm = (w >> 2) * 64, wn = (w & 3) * 64;
    #pragma unroll
    for (int mi = 0; mi < 4; ++mi)
        #pragma unroll
        for (int nf = 0; nf < 8; ++nf) {
            const int r0 = rowBase + wm + mi * 16 + (lane >> 2);
            const int c0 = colBase + wn + nf * 8 + (lane & 3) * 2;
            #pragma unroll
            for (int e = 0; e < 4; ++e)
                Cout[(size_t)(r0 + (e >> 1) * 8) * HD + c0 + (e & 1)] = acc[mi][nf][e];
        }
}

// ---------------------------------------------------------------------------
// Conversion passes
// ---------------------------------------------------------------------------
__global__ void convX(const float* __restrict__ X) {
    const size_t i = ((size_t)blockIdx.x * 256 + threadIdx.x) * 4;
    const float4 v = *(const float4*)(X + i);
    uint32_t p0 = packh2(v.x, v.y), p1 = packh2(v.z, v.w);
    uint2 pk; pk.x = p0; pk.y = p1;
    *reinterpret_cast<uint2*>(g_Xhi + i) = pk;
}

// Transpose W -> WT[n][k], fp16
__global__ void convW(const float* __restrict__ Wq, const float* __restrict__ Wk,
                      const float* __restrict__ Wv, const float* __restrict__ Wo) {
    const int z = blockIdx.z;
    const float* W = (z == 0) ? Wq : (z == 1) ? Wk : (z == 2) ? Wv : Wo;
    __half* Th = g_WThi[z];
    __shared__ float t[32][33];
    const int k0 = blockIdx.x * 32, n0 = blockIdx.y * 32;
    #pragma unroll
    for (int j = 0; j < 32; j += 8)
        t[threadIdx.y + j][threadIdx.x] = W[(size_t)(k0 + threadIdx.y + j) * HD + n0 + threadIdx.x];
    __syncthreads();
    #pragma unroll
    for (int j = 0; j < 32; j += 8) {
        const int n = n0 + threadIdx.y + j, k = k0 + threadIdx.x;
        Th[(size_t)n * D + k] = __float2half_rn(t[threadIdx.x][threadIdx.y + j]);
    }
}

// ---------------------------------------------------------------------------
// Tensor-core flash attention (causal):
// S = Qh*Kh (1-product — Q chain quantization accepted, ~2e-4/term).
// O = Ph*Vh + Pl*Vh (2-product — KEEP: 1-product PV exposed trans-LDSM
//   latency at 2 warps/SMSP and regressed in R12).
// 128 q-rows per CTA, 8 warps. 3-stage KV ring (Kh|Vh), f32 acc.
// ---------------------------------------------------------------------------
constexpr int FP     = 144;            // smem pitch (128B data + 16B pad)
constexpr int KVARR  = 64 * FP;        // 9216
constexpr int KVSTG  = 2 * KVARR;      // Kh|Vh: 18432
constexpr int QARR   = 128 * FP;       // 18432
constexpr int FSTAGES = 3;
constexpr int FSMEM  = QARR + FSTAGES * KVSTG;   // 73728

__global__ __launch_bounds__(256, 1)
void flash_mma() {
    extern __shared__ char sm[];
    const uint32_t sb = smem_u32(sm);
    const int tid = threadIdx.x, lane = tid & 31, w = tid >> 5;
    const int bh = blockIdx.y;
    const int qt = gridDim.x - 1 - blockIdx.x;        // long blocks first
    const int q0 = qt * 128;
    const int b = bh >> 4, h = bh & (H - 1);
    const int wm = w * 16;

    const __half* Qh = g_Qhi + (size_t)bh * N * DK;
    const __half* Kh = g_Khi + (size_t)bh * N * DK;
    const __half* Vh = g_Vhi + (size_t)bh * N * DK;

    const uint32_t qhiS = sb, stS = sb + QARR;

    auto load_kv = [&](int s, int j0) {
        const uint32_t base = stS + s * KVSTG;
        #pragma unroll
        for (int t = 0; t < 2; ++t) {
            const int i = tid + t * 256;
            const int r = i >> 3, ch = i & 7;
            const uint32_t off = r * FP + ch * 16;
            const size_t gi = (size_t)(j0 + r) * DK + ch * 8;
            cp16(base + off,         Kh + gi);
            cp16(base + KVARR + off, Vh + gi);
        }
    };

    const int jmax = 2 * qt + 1;

    for (int i = tid; i < 1024; i += 256) {
        const int r = i >> 3, ch = i & 7;
        cp16(qhiS + r * FP + ch * 16, Qh + (size_t)(q0 + r) * DK + ch * 8);
    }
    load_kv(0, 0);
    CP_COMMIT();
    load_kv(1, 64);
    CP_COMMIT();

    float m0 = -1e30f, m1 = -1e30f, l0 = 0.f, l1 = 0.f;
    float oAcc[8][4];
    #pragma unroll
    for (int i = 0; i < 8; ++i)
        #pragma unroll
        for (int e = 0; e < 4; ++e) oAcc[i][e] = 0.f;

    uint32_t qah[4][4];
    bool qloaded = false;
    int kvbuf = 0;

    for (int jt = 0; jt <= jmax; ++jt) {
        const int j0 = jt * 64;
        CP_WAIT(1);
        __syncthreads();
        if (jt + 2 <= jmax) {
            int nb = kvbuf + 2; if (nb >= 3) nb -= 3;
            load_kv(nb, (jt + 2) * 64);
        }
        CP_COMMIT();

        if (!qloaded) {
            #pragma unroll
            for (int kf = 0; kf < 4; ++kf) {
                const uint32_t addr = qhiS + (wm + (lane & 15)) * FP + kf * 32 + (lane >> 4) * 16;
                ldsm4(qah[kf][0], qah[kf][1], qah[kf][2], qah[kf][3], addr);
            }
            qloaded = true;
        }

        const uint32_t khS = stS + kvbuf * KVSTG;
        const uint32_t vhS = khS + KVARR;
        if (++kvbuf == 3) kvbuf = 0;

        // ---- S = Qh @ Kh^T (1-product) ----
        float s[8][4];
        #pragma unroll
        for (int i = 0; i < 8; ++i)
            #pragma unroll
            for (int e = 0; e < 4; ++e) s[i][e] = 0.f;

        #pragma unroll
        for (int kf = 0; kf < 4; ++kf) {
            uint32_t kb[4][4];
            #pragma unroll
            for (int ng = 0; ng < 4; ++ng) {
                const uint32_t addr = khS + (ng * 16 + (lane & 7) + ((lane >> 4) << 3)) * FP
                                      + kf * 32 + ((lane >> 3) & 1) * 16;
                ldsm4(kb[ng][0], kb[ng][1], kb[ng][2], kb[ng][3], addr);
            }
            #pragma unroll
            for (int ng = 0; ng < 4; ++ng)
                #pragma unroll
                for (int nf = 0; nf < 2; ++nf)
                    mma16816(s[ng * 2 + nf], qah[kf][0], qah[kf][1], qah[kf][2], qah[kf][3],
                             kb[ng][nf * 2], kb[ng][nf * 2 + 1]);
        }

        // ---- causal mask ----
        const int gr0 = q0 + wm + (lane >> 2);
        if (j0 + 64 > q0 + wm) {
            #pragma unroll
            for (int ni = 0; ni < 8; ++ni)
                #pragma unroll
                for (int e = 0; e < 4; ++e) {
                    const int col = j0 + ni * 8 + (lane & 3) * 2 + (e & 1);
                    const int row = gr0 + (e >> 1) * 8;
                    if (col > row) s[ni][e] = -1e30f;
                }
        }

        // ---- online softmax ----
        float rm0 = -1e30f, rm1 = -1e30f;
        #pragma unroll
        for (int ni = 0; ni < 8; ++ni) {
            rm0 = fmaxf(rm0, fmaxf(s[ni][0], s[ni][1]));
            rm1 = fmaxf(rm1, fmaxf(s[ni][2], s[ni][3]));
        }
        rm0 = fmaxf(rm0, __shfl_xor_sync(0xffffffffu, rm0, 1));
        rm0 = fmaxf(rm0, __shfl_xor_sync(0xffffffffu, rm0, 2));
        rm1 = fmaxf(rm1, __shfl_xor_sync(0xffffffffu, rm1, 1));
        rm1 = fmaxf(rm1, __shfl_xor_sync(0xffffffffu, rm1, 2));

        const float mn0 = fmaxf(m0, rm0), mn1 = fmaxf(m1, rm1);
        const float a0 = __expf(m0 - mn0), a1 = __expf(m1 - mn1);
        m0 = mn0; m1 = mn1;

        float rs0 = 0.f, rs1 = 0.f;
        #pragma unroll
        for (int ni = 0; ni < 8; ++ni) {
            s[ni][0] = __expf(s[ni][0] - mn0); rs0 += s[ni][0];
            s[ni][1] = __expf(s[ni][1] - mn0); rs0 += s[ni][1];
            s[ni][2] = __expf(s[ni][2] - mn1); rs1 += s[ni][2];
            s[ni][3] = __expf(s[ni][3] - mn1); rs1 += s[ni][3];
        }
        rs0 += __shfl_xor_sync(0xffffffffu, rs0, 1);
        rs0 += __shfl_xor_sync(0xffffffffu, rs0, 2);
        rs1 += __shfl_xor_sync(0xffffffffu, rs1, 1);
        rs1 += __shfl_xor_sync(0xffffffffu, rs1, 2);
        l0 = l0 * a0 + rs0;
        l1 = l1 * a1 + rs1;

        #pragma unroll
        for (int ni = 0; ni < 8; ++ni) {
            oAcc[ni][0] *= a0; oAcc[ni][1] *= a0;
            oAcc[ni][2] *= a1; oAcc[ni][3] *= a1;
        }

        // ---- P -> fp16 hi/lo A-fragments (register-only) ----
        uint32_t pah[4][4], pal[4][4];
        #pragma unroll
        for (int kf = 0; kf < 4; ++kf) {
            pah[kf][0] = packsplit(s[2 * kf][0],     s[2 * kf][1],     pal[kf][0]);
            pah[kf][1] = packsplit(s[2 * kf][2],     s[2 * kf][3],     pal[kf][1]);
            pah[kf][2] = packsplit(s[2 * kf + 1][0], s[2 * kf + 1][1], pal[kf][2]);
            pah[kf][3] = packsplit(s[2 * kf + 1][2], s[2 * kf + 1][3], pal[kf][3]);
        }

        // ---- O += (Ph + Pl) @ Vh ----
        #pragma unroll
        for (int kf = 0; kf < 4; ++kf) {
            uint32_t vb[4][4];
            #pragma unroll
            for (int ng = 0; ng < 4; ++ng) {
                const uint32_t addr = vhS + (kf * 16 + (lane & 15)) * FP
                                      + ng * 32 + (lane >> 4) * 16;
                ldsm4t(vb[ng][0], vb[ng][1], vb[ng][2], vb[ng][3], addr);
            }
            #pragma unroll
            for (int ng = 0; ng < 4; ++ng)
                #pragma unroll
                for (int nf = 0; nf < 2; ++nf)
                    mma16816(oAcc[ng * 2 + nf], pah[kf][0], pah[kf][1], pah[kf][2], pah[kf][3],
                             vb[ng][nf * 2], vb[ng][nf * 2 + 1]);
            #pragma unroll
            for (int ng = 0; ng < 4; ++ng)
                #pragma unroll
                for (int nf = 0; nf < 2; ++nf)
                    mma16816(oAcc[ng * 2 + nf], pal[kf][0], pal[kf][1], pal[kf][2], pal[kf][3],
                             vb[ng][nf * 2], vb[ng][nf * 2 + 1]);
        }
        // no trailing sync: 3-stage ring + top-of-loop barrier covers reuse
    }

    // ---- epilogue: normalize, split to fp16 hi/lo for output projection ----
    const float inv0 = 1.0f / l0, inv1 = 1.0f / l1;
    const int r0 = q0 + wm + (lane >> 2);
    #pragma unroll
    for (int ni = 0; ni < 8; ++ni) {
        const int col = h * DK + ni * 8 + (lane & 3) * 2;
        uint32_t lo;
        uint32_t hi = packsplit(oAcc[ni][0] * inv0, oAcc[ni][1] * inv0, lo);
        size_t idx = ((size_t)b * N + r0) * HD + col;
        *reinterpret_cast<uint32_t*>(g_AThi + idx) = hi;
        *reinterpret_cast<uint32_t*>(g_ATlo + idx) = lo;
        hi = packsplit(oAcc[ni][2] * inv1, oAcc[ni][3] * inv1, lo);
        idx = ((size_t)b * N + r0 + 8) * HD + col;
        *reinterpret_cast<uint32_t*>(g_AThi + idx) = hi;
        *reinterpret_cast<uint32_t*>(g_ATlo + idx) = lo;
    }
}

// ---------------------------------------------------------------------------
extern "C" void kernel_launch(void* const* d_in, const int* in_sizes, int n_in,
                              void* d_out, int out_size) {
    const float* X  = (const float*)d_in[0];
    // d_in[1] = mask (pure causal -> applied analytically)
    const float* Wq = (const float*)d_in[2];
    const float* Wk = (const float*)d_in[3];
    const float* Wv = (const float*)d_in[4];
    const float* Wo = (const float*)d_in[5];
    float* out = (float*)d_out;

    cudaFuncSetAttribute(qkv_mma,   cudaFuncAttributeMaxDynamicSharedMemorySize, GSMEM_QKV);
    cudaFuncSetAttribute(out_mma,   cudaFuncAttributeMaxDynamicSharedMemorySize, GSMEM_OUT);
    cudaFuncSetAttribute(flash_mma, cudaFuncAttributeMaxDynamicSharedMemorySize, FSMEM);

    // 0) conversions
    convX<<<(B * N * D / 4) / 256, 256>>>(X);
    convW<<<dim3(D / 32, HD / 32, 4), dim3(32, 8)>>>(Wq, Wk, Wv, Wo);

    // 1) QKV projections (1-product fp16, 128x256 tiles)
    qkv_mma<<<dim3(HD / 256, (B * N) / 128, 3), 256, GSMEM_QKV>>>();   // (4, 64, 3)

    // 2) causal flash attention (S 1-product, PV 2-product)
    flash_mma<<<dim3(N / 128, B * H), 256, FSMEM>>>();                 // (16, 64)

    // 3) output projection (2-product, AT-corrected, 128x256 tiles)
    out_mma<<<dim3(HD / 256, (B * N) / 128), 256, GSMEM_OUT>>>(out);   // (4, 64)
}